// round 2
// baseline (speedup 1.0000x reference)
#include <cuda_runtime.h>
#include <cstdint>

#define EPSV  1e-5f
#define SLOPE 0.01f

// ---------------- scratch (static device memory; no allocs allowed) ----------------
__device__ float g_h[(size_t)64 * 96 * 56 * 56];     // stem output (77 MB)
__device__ float g_off[(size_t)64 * 32 * 14 * 14];   // offsets
__device__ float g_B[(size_t)12544 * 1536];          // gathered sample matrix B[n][k] (77 MB)

// ---------------- packed f32x2 helpers ----------------
__device__ __forceinline__ unsigned long long pk2(float x, float y) {
    unsigned long long r;
    asm("mov.b64 %0,{%1,%2};" : "=l"(r) : "f"(x), "f"(y));
    return r;
}
__device__ __forceinline__ unsigned long long fma2(unsigned long long a,
                                                   unsigned long long b,
                                                   unsigned long long c) {
    unsigned long long d;
    asm("fma.rn.f32x2 %0,%1,%2,%3;" : "=l"(d) : "l"(a), "l"(b), "l"(c));
    return d;
}
__device__ __forceinline__ void upk2(unsigned long long v, float& lo, float& hi) {
    asm("mov.b64 {%0,%1},%2;" : "=f"(lo), "=f"(hi) : "l"(v));
}

__device__ __forceinline__ float lrelu(float x) { return x >= 0.f ? x : SLOPE * x; }

// =====================================================================================
// K1: stem conv (4x4 stride4 VALID) + BN1 + leaky ReLU, fused.
// Non-overlapping patches -> each thread owns one spatial position's 48-value patch
// in registers and computes 24 output channels (4 at a time via float4 smem weights).
// grid = 64 batches * 49 spatial blocks, 256 threads (64 spatial x 4 channel quarters)
// =====================================================================================
__global__ __launch_bounds__(256) void stem_kernel(
    const float* __restrict__ x, const float* __restrict__ sw, const float* __restrict__ sb,
    const float* __restrict__ bg, const float* __restrict__ bb, const float* __restrict__ bm,
    const float* __restrict__ bv)
{
    __shared__ float wst[48][96];   // wst[k][co] = stem_w[co][k] * scale[co]
    __shared__ float s_sc[96];
    __shared__ float s_bb[96];

    int tid = threadIdx.x;
    for (int i = tid; i < 96; i += 256) {
        float sc = bg[i] * rsqrtf(bv[i] + EPSV);
        s_sc[i] = sc;
        s_bb[i] = sb[i] * sc + bb[i] - bm[i] * sc;   // folded conv-bias + BN shift
    }
    __syncthreads();
    for (int i = tid; i < 96 * 48; i += 256) {
        int co = i / 48, k = i % 48;
        wst[k][co] = sw[i] * s_sc[co];
    }
    __syncthreads();

    int b = blockIdx.x / 49;
    int s = (blockIdx.x % 49) * 64 + (tid & 63);   // 0..3135
    int quarter = tid >> 6;                        // 0..3 (24 co each)
    int oh = s / 56, ow = s % 56;

    float patch[48];
    const float* xb = x + (size_t)b * 3 * 224 * 224;
#pragma unroll
    for (int ci = 0; ci < 3; ci++)
#pragma unroll
        for (int r = 0; r < 4; r++) {
            float4 p4 = *(const float4*)(xb + ((size_t)ci * 224 + oh * 4 + r) * 224 + ow * 4);
            patch[ci * 16 + r * 4 + 0] = p4.x;
            patch[ci * 16 + r * 4 + 1] = p4.y;
            patch[ci * 16 + r * 4 + 2] = p4.z;
            patch[ci * 16 + r * 4 + 3] = p4.w;
        }

    float* hb = g_h + (size_t)b * 96 * 3136 + s;
#pragma unroll
    for (int gq = 0; gq < 6; gq++) {
        int co = quarter * 24 + gq * 4;
        float a0 = s_bb[co], a1 = s_bb[co + 1], a2 = s_bb[co + 2], a3 = s_bb[co + 3];
#pragma unroll
        for (int k = 0; k < 48; k++) {
            float4 w4 = *(const float4*)&wst[k][co];
            float pv = patch[k];
            a0 += pv * w4.x; a1 += pv * w4.y; a2 += pv * w4.z; a3 += pv * w4.w;
        }
        hb[(size_t)(co + 0) * 3136] = lrelu(a0);
        hb[(size_t)(co + 1) * 3136] = lrelu(a1);
        hb[(size_t)(co + 2) * 3136] = lrelu(a2);
        hb[(size_t)(co + 3) * 3136] = lrelu(a3);
    }
}

// =====================================================================================
// K2: offset conv (96->32, 4x4 stride4). One block per (b, oh, ow); patch in smem;
// 8 warps x 4 channels each, warp-strided dot + shuffle reduce.
// =====================================================================================
__global__ __launch_bounds__(256) void offconv_kernel(
    const float* __restrict__ w_, const float* __restrict__ b_)
{
    __shared__ float patch[1536];
    int bp = blockIdx.x;
    int b = bp / 196, p = bp % 196;
    int oh = p / 14, ow = p % 14;
    int tid = threadIdx.x;

    for (int e = tid; e < 1536; e += 256) {
        int c = e >> 4, r = (e >> 2) & 3, cc = e & 3;
        patch[e] = g_h[(((size_t)b * 96 + c) * 56 + oh * 4 + r) * 56 + ow * 4 + cc];
    }
    __syncthreads();

    int warp = tid >> 5, lane = tid & 31;
#pragma unroll
    for (int q = 0; q < 4; q++) {
        int co = warp * 4 + q;
        const float* w = w_ + (size_t)co * 1536;
        float s = 0.f;
#pragma unroll 8
        for (int k = lane; k < 1536; k += 32) s += patch[k] * w[k];
#pragma unroll
        for (int o = 16; o; o >>= 1) s += __shfl_down_sync(0xffffffffu, s, o);
        if (lane == 0)
            g_off[(((size_t)b * 32 + co) * 14 + oh) * 14 + ow] = s + b_[co];
    }
}

// =====================================================================================
// K3a: bilinear gather -> B[n][k], n = b*196 + p (column of the deform GEMM),
// k = c*16 + kk. Coords computed once per (b,p) into smem; writes coalesced along k.
// =====================================================================================
__global__ __launch_bounds__(256) void gather_kernel()
{
    __shared__ float s_wy[16], s_wx[16];
    __shared__ int   s_y0[16], s_x0[16];

    int bp = blockIdx.x;
    int b = bp / 196, p = bp % 196;
    int oh = p / 14, ow = p % 14;
    int tid = threadIdx.x;

    if (tid < 16) {
        int kk = tid;
        float o0 = g_off[(((size_t)b * 32 + 2 * kk + 0) * 14 + oh) * 14 + ow];
        float o1 = g_off[(((size_t)b * 32 + 2 * kk + 1) * 14 + oh) * 14 + ow];
        float py = (float)(oh * 4 + (kk >> 2)) + o0;
        float px = (float)(ow * 4 + (kk & 3)) + o1;
        float y0f = floorf(py), x0f = floorf(px);
        s_y0[kk] = (int)y0f; s_x0[kk] = (int)x0f;
        s_wy[kk] = py - y0f; s_wx[kk] = px - x0f;
    }
    __syncthreads();

    const float* hb = g_h + (size_t)b * 96 * 3136;
    float* Brow = g_B + (size_t)bp * 1536;

    for (int e = tid; e < 1536; e += 256) {
        int c = e >> 4, kk = e & 15;
        int y0 = s_y0[kk], x0 = s_x0[kk];
        float wy = s_wy[kk], wx = s_wx[kk];
        const float* hc = hb + (size_t)c * 3136;

        int y1 = y0 + 1, x1 = x0 + 1;
        bool vy0 = (y0 >= 0) & (y0 < 56), vy1 = (y1 >= 0) & (y1 < 56);
        bool vx0 = (x0 >= 0) & (x0 < 56), vx1 = (x1 >= 0) & (x1 < 56);
        int yc0 = min(max(y0, 0), 55), yc1 = min(max(y1, 0), 55);
        int xc0 = min(max(x0, 0), 55), xc1 = min(max(x1, 0), 55);

        float v00 = (vy0 & vx0) ? hc[yc0 * 56 + xc0] : 0.f;
        float v01 = (vy0 & vx1) ? hc[yc0 * 56 + xc1] : 0.f;
        float v10 = (vy1 & vx0) ? hc[yc1 * 56 + xc0] : 0.f;
        float v11 = (vy1 & vx1) ? hc[yc1 * 56 + xc1] : 0.f;

        Brow[e] = v00 * (1.f - wy) * (1.f - wx) + v01 * (1.f - wy) * wx
                + v10 * wy * (1.f - wx)        + v11 * wy * wx;
    }
}

// =====================================================================================
// K3b: SGEMM C[o][n] = sum_k A[o][k] * B[n][k], M=768, N=12544, K=1536.
// 128x128 block tile, BK=16, 256 threads, 8x8 microtile, packed fma.rn.f32x2 inner loop.
// Fused epilogue: +dcn_b, BN2, leaky ReLU, transposed store out[n*768 + o].
// =====================================================================================
__global__ __launch_bounds__(256) void dgemm_kernel(
    const float* __restrict__ A,   // dcn_w flat [768][1536]
    const float* __restrict__ db,  // dcn_b
    const float* __restrict__ bg, const float* __restrict__ bb,
    const float* __restrict__ bm, const float* __restrict__ bv,
    float* __restrict__ out)
{
    __shared__ float As[16][128];
    __shared__ float Bs[16][128];

    int tid = threadIdx.x;
    int tx = tid & 15;       // n-dim microtile index
    int ty = tid >> 4;       // o-dim microtile index
    int obase = blockIdx.y * 128;
    int nbase = blockIdx.x * 128;

    int lr = tid >> 2;           // 0..63 tile row for loading
    int lc = (tid & 3) * 4;      // k offset 0/4/8/12

    unsigned long long acc2[8][4];
#pragma unroll
    for (int i = 0; i < 8; i++)
#pragma unroll
        for (int j = 0; j < 4; j++) acc2[i][j] = 0ull;

    for (int k0 = 0; k0 < 1536; k0 += 16) {
        // load A tile (128 rows x 16 k), store transposed
        float4 a0 = *(const float4*)&A[(size_t)(obase + lr)      * 1536 + k0 + lc];
        float4 a1 = *(const float4*)&A[(size_t)(obase + lr + 64) * 1536 + k0 + lc];
        As[lc + 0][lr] = a0.x; As[lc + 1][lr] = a0.y; As[lc + 2][lr] = a0.z; As[lc + 3][lr] = a0.w;
        As[lc + 0][lr + 64] = a1.x; As[lc + 1][lr + 64] = a1.y; As[lc + 2][lr + 64] = a1.z; As[lc + 3][lr + 64] = a1.w;
        // load B tile (128 n-rows x 16 k), store transposed
        float4 b0 = *(const float4*)&g_B[(size_t)(nbase + lr)      * 1536 + k0 + lc];
        float4 b1 = *(const float4*)&g_B[(size_t)(nbase + lr + 64) * 1536 + k0 + lc];
        Bs[lc + 0][lr] = b0.x; Bs[lc + 1][lr] = b0.y; Bs[lc + 2][lr] = b0.z; Bs[lc + 3][lr] = b0.w;
        Bs[lc + 0][lr + 64] = b1.x; Bs[lc + 1][lr + 64] = b1.y; Bs[lc + 2][lr + 64] = b1.z; Bs[lc + 3][lr + 64] = b1.w;
        __syncthreads();

#pragma unroll
        for (int kk = 0; kk < 16; kk++) {
            float4 af0 = *(const float4*)&As[kk][ty * 8];
            float4 af1 = *(const float4*)&As[kk][ty * 8 + 4];
            float4 bf0 = *(const float4*)&Bs[kk][tx * 8];
            float4 bf1 = *(const float4*)&Bs[kk][tx * 8 + 4];
            unsigned long long b2[4] = { pk2(bf0.x, bf0.y), pk2(bf0.z, bf0.w),
                                         pk2(bf1.x, bf1.y), pk2(bf1.z, bf1.w) };
            float av[8] = { af0.x, af0.y, af0.z, af0.w, af1.x, af1.y, af1.z, af1.w };
#pragma unroll
            for (int i = 0; i < 8; i++) {
                unsigned long long ai2 = pk2(av[i], av[i]);
#pragma unroll
                for (int j = 0; j < 4; j++)
                    acc2[i][j] = fma2(ai2, b2[j], acc2[i][j]);
            }
        }
        __syncthreads();
    }

    // epilogue: unpack, BN2 + bias + lrelu, transposed store
    float cf[8][8];
#pragma unroll
    for (int i = 0; i < 8; i++)
#pragma unroll
        for (int j = 0; j < 4; j++)
            upk2(acc2[i][j], cf[i][2 * j], cf[i][2 * j + 1]);

    float sc[8], sh[8];
#pragma unroll
    for (int i = 0; i < 8; i++) {
        int o = obase + ty * 8 + i;
        float s = bg[o] * rsqrtf(bv[o] + EPSV);
        sc[i] = s;
        sh[i] = db[o] * s + bb[o] - bm[o] * s;
    }

#pragma unroll
    for (int j = 0; j < 8; j++) {
        int n = nbase + tx * 8 + j;
        float* op = out + (size_t)n * 768 + obase + ty * 8;
        float4 v0, v1;
        float t0 = lrelu(cf[0][j] * sc[0] + sh[0]);
        float t1 = lrelu(cf[1][j] * sc[1] + sh[1]);
        float t2 = lrelu(cf[2][j] * sc[2] + sh[2]);
        float t3 = lrelu(cf[3][j] * sc[3] + sh[3]);
        float t4 = lrelu(cf[4][j] * sc[4] + sh[4]);
        float t5 = lrelu(cf[5][j] * sc[5] + sh[5]);
        float t6 = lrelu(cf[6][j] * sc[6] + sh[6]);
        float t7 = lrelu(cf[7][j] * sc[7] + sh[7]);
        v0.x = t0; v0.y = t1; v0.z = t2; v0.w = t3;
        v1.x = t4; v1.y = t5; v1.z = t6; v1.w = t7;
        *(float4*)op = v0;
        *(float4*)(op + 4) = v1;
    }
}

// =====================================================================================
extern "C" void kernel_launch(void* const* d_in, const int* in_sizes, int n_in,
                              void* d_out, int out_size)
{
    const float* x      = (const float*)d_in[0];
    const float* stem_w = (const float*)d_in[1];
    const float* stem_b = (const float*)d_in[2];
    const float* bn1_g  = (const float*)d_in[3];
    const float* bn1_b  = (const float*)d_in[4];
    const float* bn1_m  = (const float*)d_in[5];
    const float* bn1_v  = (const float*)d_in[6];
    const float* off_w  = (const float*)d_in[7];
    const float* off_b  = (const float*)d_in[8];
    const float* dcn_w  = (const float*)d_in[9];
    const float* dcn_b  = (const float*)d_in[10];
    const float* bn2_g  = (const float*)d_in[11];
    const float* bn2_b  = (const float*)d_in[12];
    const float* bn2_m  = (const float*)d_in[13];
    const float* bn2_v  = (const float*)d_in[14];
    float* out = (float*)d_out;

    stem_kernel<<<64 * 49, 256>>>(x, stem_w, stem_b, bn1_g, bn1_b, bn1_m, bn1_v);
    offconv_kernel<<<64 * 196, 256>>>(off_w, off_b);
    gather_kernel<<<64 * 196, 256>>>();
    dgemm_kernel<<<dim3(98, 6), 256>>>(dcn_w, dcn_b, bn2_g, bn2_b, bn2_m, bn2_v, out);
}

// round 3
// speedup vs baseline: 1.0017x; 1.0017x over previous
#include <cuda_runtime.h>
#include <cstdint>

#define EPSV  1e-5f
#define SLOPE 0.01f

// ---------------- scratch (static device memory; no allocs allowed) ----------------
__device__ float g_h[(size_t)64 * 96 * 56 * 56];     // stem output (77 MB)
__device__ float g_off[(size_t)64 * 32 * 14 * 14];   // offsets
__device__ float g_B[(size_t)12544 * 1536];          // gathered sample matrix B[n][k] (77 MB)

// ---------------- packed f32x2 helpers ----------------
__device__ __forceinline__ unsigned long long pk2(float x, float y) {
    unsigned long long r;
    asm("mov.b64 %0,{%1,%2};" : "=l"(r) : "f"(x), "f"(y));
    return r;
}
__device__ __forceinline__ unsigned long long fma2(unsigned long long a,
                                                   unsigned long long b,
                                                   unsigned long long c) {
    unsigned long long d;
    asm("fma.rn.f32x2 %0,%1,%2,%3;" : "=l"(d) : "l"(a), "l"(b), "l"(c));
    return d;
}
__device__ __forceinline__ void upk2(unsigned long long v, float& lo, float& hi) {
    asm("mov.b64 {%0,%1},%2;" : "=f"(lo), "=f"(hi) : "l"(v));
}

__device__ __forceinline__ float lrelu(float x) { return x >= 0.f ? x : SLOPE * x; }

// =====================================================================================
// K1: stem conv (4x4 stride4 VALID) + BN1 + leaky ReLU, fused.
// Non-overlapping patches -> each thread owns one spatial position's 48-value patch
// in registers and computes 24 output channels (4 at a time via float4 smem weights).
// grid = 64 batches * 49 spatial blocks, 256 threads (64 spatial x 4 channel quarters)
// =====================================================================================
__global__ __launch_bounds__(256) void stem_kernel(
    const float* __restrict__ x, const float* __restrict__ sw, const float* __restrict__ sb,
    const float* __restrict__ bg, const float* __restrict__ bb, const float* __restrict__ bm,
    const float* __restrict__ bv)
{
    __shared__ float wst[48][96];   // wst[k][co] = stem_w[co][k] * scale[co]
    __shared__ float s_sc[96];
    __shared__ float s_bb[96];

    int tid = threadIdx.x;
    for (int i = tid; i < 96; i += 256) {
        float sc = bg[i] * rsqrtf(bv[i] + EPSV);
        s_sc[i] = sc;
        s_bb[i] = sb[i] * sc + bb[i] - bm[i] * sc;   // folded conv-bias + BN shift
    }
    __syncthreads();
    for (int i = tid; i < 96 * 48; i += 256) {
        int co = i / 48, k = i % 48;
        wst[k][co] = sw[i] * s_sc[co];
    }
    __syncthreads();

    int b = blockIdx.x / 49;
    int s = (blockIdx.x % 49) * 64 + (tid & 63);   // 0..3135
    int quarter = tid >> 6;                        // 0..3 (24 co each)
    int oh = s / 56, ow = s % 56;

    float patch[48];
    const float* xb = x + (size_t)b * 3 * 224 * 224;
#pragma unroll
    for (int ci = 0; ci < 3; ci++)
#pragma unroll
        for (int r = 0; r < 4; r++) {
            float4 p4 = *(const float4*)(xb + ((size_t)ci * 224 + oh * 4 + r) * 224 + ow * 4);
            patch[ci * 16 + r * 4 + 0] = p4.x;
            patch[ci * 16 + r * 4 + 1] = p4.y;
            patch[ci * 16 + r * 4 + 2] = p4.z;
            patch[ci * 16 + r * 4 + 3] = p4.w;
        }

    float* hb = g_h + (size_t)b * 96 * 3136 + s;
#pragma unroll
    for (int gq = 0; gq < 6; gq++) {
        int co = quarter * 24 + gq * 4;
        float a0 = s_bb[co], a1 = s_bb[co + 1], a2 = s_bb[co + 2], a3 = s_bb[co + 3];
#pragma unroll
        for (int k = 0; k < 48; k++) {
            float4 w4 = *(const float4*)&wst[k][co];
            float pv = patch[k];
            a0 += pv * w4.x; a1 += pv * w4.y; a2 += pv * w4.z; a3 += pv * w4.w;
        }
        hb[(size_t)(co + 0) * 3136] = lrelu(a0);
        hb[(size_t)(co + 1) * 3136] = lrelu(a1);
        hb[(size_t)(co + 2) * 3136] = lrelu(a2);
        hb[(size_t)(co + 3) * 3136] = lrelu(a3);
    }
}

// =====================================================================================
// K2: offset conv (96->32, 4x4 stride4). One block per (b, oh, ow); patch in smem;
// 8 warps x 4 channels each, warp-strided dot + shuffle reduce.
// =====================================================================================
__global__ __launch_bounds__(256) void offconv_kernel(
    const float* __restrict__ w_, const float* __restrict__ b_)
{
    __shared__ float patch[1536];
    int bp = blockIdx.x;
    int b = bp / 196, p = bp % 196;
    int oh = p / 14, ow = p % 14;
    int tid = threadIdx.x;

    for (int e = tid; e < 1536; e += 256) {
        int c = e >> 4, r = (e >> 2) & 3, cc = e & 3;
        patch[e] = g_h[(((size_t)b * 96 + c) * 56 + oh * 4 + r) * 56 + ow * 4 + cc];
    }
    __syncthreads();

    int warp = tid >> 5, lane = tid & 31;
#pragma unroll
    for (int q = 0; q < 4; q++) {
        int co = warp * 4 + q;
        const float* w = w_ + (size_t)co * 1536;
        float s = 0.f;
#pragma unroll 8
        for (int k = lane; k < 1536; k += 32) s += patch[k] * w[k];
#pragma unroll
        for (int o = 16; o; o >>= 1) s += __shfl_down_sync(0xffffffffu, s, o);
        if (lane == 0)
            g_off[(((size_t)b * 32 + co) * 14 + oh) * 14 + ow] = s + b_[co];
    }
}

// =====================================================================================
// K3a: bilinear gather -> B[n][k], n = b*196 + p (column of the deform GEMM),
// k = c*16 + kk. Coords computed once per (b,p) into smem; writes coalesced along k.
// =====================================================================================
__global__ __launch_bounds__(256) void gather_kernel()
{
    __shared__ float s_wy[16], s_wx[16];
    __shared__ int   s_y0[16], s_x0[16];

    int bp = blockIdx.x;
    int b = bp / 196, p = bp % 196;
    int oh = p / 14, ow = p % 14;
    int tid = threadIdx.x;

    if (tid < 16) {
        int kk = tid;
        float o0 = g_off[(((size_t)b * 32 + 2 * kk + 0) * 14 + oh) * 14 + ow];
        float o1 = g_off[(((size_t)b * 32 + 2 * kk + 1) * 14 + oh) * 14 + ow];
        float py = (float)(oh * 4 + (kk >> 2)) + o0;
        float px = (float)(ow * 4 + (kk & 3)) + o1;
        float y0f = floorf(py), x0f = floorf(px);
        s_y0[kk] = (int)y0f; s_x0[kk] = (int)x0f;
        s_wy[kk] = py - y0f; s_wx[kk] = px - x0f;
    }
    __syncthreads();

    const float* hb = g_h + (size_t)b * 96 * 3136;
    float* Brow = g_B + (size_t)bp * 1536;

    for (int e = tid; e < 1536; e += 256) {
        int c = e >> 4, kk = e & 15;
        int y0 = s_y0[kk], x0 = s_x0[kk];
        float wy = s_wy[kk], wx = s_wx[kk];
        const float* hc = hb + (size_t)c * 3136;

        int y1 = y0 + 1, x1 = x0 + 1;
        bool vy0 = (y0 >= 0) & (y0 < 56), vy1 = (y1 >= 0) & (y1 < 56);
        bool vx0 = (x0 >= 0) & (x0 < 56), vx1 = (x1 >= 0) & (x1 < 56);
        int yc0 = min(max(y0, 0), 55), yc1 = min(max(y1, 0), 55);
        int xc0 = min(max(x0, 0), 55), xc1 = min(max(x1, 0), 55);

        float v00 = (vy0 & vx0) ? hc[yc0 * 56 + xc0] : 0.f;
        float v01 = (vy0 & vx1) ? hc[yc0 * 56 + xc1] : 0.f;
        float v10 = (vy1 & vx0) ? hc[yc1 * 56 + xc0] : 0.f;
        float v11 = (vy1 & vx1) ? hc[yc1 * 56 + xc1] : 0.f;

        Brow[e] = v00 * (1.f - wy) * (1.f - wx) + v01 * (1.f - wy) * wx
                + v10 * wy * (1.f - wx)        + v11 * wy * wx;
    }
}

// =====================================================================================
// K3b: SGEMM C[o][n] = sum_k A[o][k] * B[n][k], M=768, N=12544, K=1536.
// 128x128 block tile, BK=16, 256 threads, 8x8 microtile, packed fma.rn.f32x2 inner loop.
// Fused epilogue: +dcn_b, BN2, leaky ReLU, transposed store out[n*768 + o].
// =====================================================================================
__global__ __launch_bounds__(256) void dgemm_kernel(
    const float* __restrict__ A,   // dcn_w flat [768][1536]
    const float* __restrict__ db,  // dcn_b
    const float* __restrict__ bg, const float* __restrict__ bb,
    const float* __restrict__ bm, const float* __restrict__ bv,
    float* __restrict__ out)
{
    __shared__ float As[16][128];
    __shared__ float Bs[16][128];

    int tid = threadIdx.x;
    int tx = tid & 15;       // n-dim microtile index
    int ty = tid >> 4;       // o-dim microtile index
    int obase = blockIdx.y * 128;
    int nbase = blockIdx.x * 128;

    int lr = tid >> 2;           // 0..63 tile row for loading
    int lc = (tid & 3) * 4;      // k offset 0/4/8/12

    unsigned long long acc2[8][4];
#pragma unroll
    for (int i = 0; i < 8; i++)
#pragma unroll
        for (int j = 0; j < 4; j++) acc2[i][j] = 0ull;

    for (int k0 = 0; k0 < 1536; k0 += 16) {
        // load A tile (128 rows x 16 k), store transposed
        float4 a0 = *(const float4*)&A[(size_t)(obase + lr)      * 1536 + k0 + lc];
        float4 a1 = *(const float4*)&A[(size_t)(obase + lr + 64) * 1536 + k0 + lc];
        As[lc + 0][lr] = a0.x; As[lc + 1][lr] = a0.y; As[lc + 2][lr] = a0.z; As[lc + 3][lr] = a0.w;
        As[lc + 0][lr + 64] = a1.x; As[lc + 1][lr + 64] = a1.y; As[lc + 2][lr + 64] = a1.z; As[lc + 3][lr + 64] = a1.w;
        // load B tile (128 n-rows x 16 k), store transposed
        float4 b0 = *(const float4*)&g_B[(size_t)(nbase + lr)      * 1536 + k0 + lc];
        float4 b1 = *(const float4*)&g_B[(size_t)(nbase + lr + 64) * 1536 + k0 + lc];
        Bs[lc + 0][lr] = b0.x; Bs[lc + 1][lr] = b0.y; Bs[lc + 2][lr] = b0.z; Bs[lc + 3][lr] = b0.w;
        Bs[lc + 0][lr + 64] = b1.x; Bs[lc + 1][lr + 64] = b1.y; Bs[lc + 2][lr + 64] = b1.z; Bs[lc + 3][lr + 64] = b1.w;
        __syncthreads();

#pragma unroll
        for (int kk = 0; kk < 16; kk++) {
            float4 af0 = *(const float4*)&As[kk][ty * 8];
            float4 af1 = *(const float4*)&As[kk][ty * 8 + 4];
            float4 bf0 = *(const float4*)&Bs[kk][tx * 8];
            float4 bf1 = *(const float4*)&Bs[kk][tx * 8 + 4];
            unsigned long long b2[4] = { pk2(bf0.x, bf0.y), pk2(bf0.z, bf0.w),
                                         pk2(bf1.x, bf1.y), pk2(bf1.z, bf1.w) };
            float av[8] = { af0.x, af0.y, af0.z, af0.w, af1.x, af1.y, af1.z, af1.w };
#pragma unroll
            for (int i = 0; i < 8; i++) {
                unsigned long long ai2 = pk2(av[i], av[i]);
#pragma unroll
                for (int j = 0; j < 4; j++)
                    acc2[i][j] = fma2(ai2, b2[j], acc2[i][j]);
            }
        }
        __syncthreads();
    }

    // epilogue: unpack, BN2 + bias + lrelu, transposed store
    float cf[8][8];
#pragma unroll
    for (int i = 0; i < 8; i++)
#pragma unroll
        for (int j = 0; j < 4; j++)
            upk2(acc2[i][j], cf[i][2 * j], cf[i][2 * j + 1]);

    float sc[8], sh[8];
#pragma unroll
    for (int i = 0; i < 8; i++) {
        int o = obase + ty * 8 + i;
        float s = bg[o] * rsqrtf(bv[o] + EPSV);
        sc[i] = s;
        sh[i] = db[o] * s + bb[o] - bm[o] * s;
    }

#pragma unroll
    for (int j = 0; j < 8; j++) {
        int n = nbase + tx * 8 + j;
        float* op = out + (size_t)n * 768 + obase + ty * 8;
        float4 v0, v1;
        float t0 = lrelu(cf[0][j] * sc[0] + sh[0]);
        float t1 = lrelu(cf[1][j] * sc[1] + sh[1]);
        float t2 = lrelu(cf[2][j] * sc[2] + sh[2]);
        float t3 = lrelu(cf[3][j] * sc[3] + sh[3]);
        float t4 = lrelu(cf[4][j] * sc[4] + sh[4]);
        float t5 = lrelu(cf[5][j] * sc[5] + sh[5]);
        float t6 = lrelu(cf[6][j] * sc[6] + sh[6]);
        float t7 = lrelu(cf[7][j] * sc[7] + sh[7]);
        v0.x = t0; v0.y = t1; v0.z = t2; v0.w = t3;
        v1.x = t4; v1.y = t5; v1.z = t6; v1.w = t7;
        *(float4*)op = v0;
        *(float4*)(op + 4) = v1;
    }
}

// =====================================================================================
extern "C" void kernel_launch(void* const* d_in, const int* in_sizes, int n_in,
                              void* d_out, int out_size)
{
    const float* x      = (const float*)d_in[0];
    const float* stem_w = (const float*)d_in[1];
    const float* stem_b = (const float*)d_in[2];
    const float* bn1_g  = (const float*)d_in[3];
    const float* bn1_b  = (const float*)d_in[4];
    const float* bn1_m  = (const float*)d_in[5];
    const float* bn1_v  = (const float*)d_in[6];
    const float* off_w  = (const float*)d_in[7];
    const float* off_b  = (const float*)d_in[8];
    const float* dcn_w  = (const float*)d_in[9];
    const float* dcn_b  = (const float*)d_in[10];
    const float* bn2_g  = (const float*)d_in[11];
    const float* bn2_b  = (const float*)d_in[12];
    const float* bn2_m  = (const float*)d_in[13];
    const float* bn2_v  = (const float*)d_in[14];
    float* out = (float*)d_out;

    stem_kernel<<<64 * 49, 256>>>(x, stem_w, stem_b, bn1_g, bn1_b, bn1_m, bn1_v);
    offconv_kernel<<<64 * 196, 256>>>(off_w, off_b);
    gather_kernel<<<64 * 196, 256>>>();
    dgemm_kernel<<<dim3(98, 6), 256>>>(dcn_w, dcn_b, bn2_g, bn2_b, bn2_m, bn2_v, out);
}

// round 8
// speedup vs baseline: 1.9108x; 1.9076x over previous
#include <cuda_runtime.h>
#include <cuda_bf16.h>
#include <cstdint>

#define EPSV  1e-5f
#define SLOPE 0.01f

// ---------------- scratch (static device memory; no allocs allowed) ----------------
__device__ float g_h[(size_t)64 * 96 * 56 * 56];       // stem output (77 MB)
__device__ float g_off[(size_t)64 * 32 * 14 * 14];     // offsets
__device__ __nv_bfloat16 g_Bhi[(size_t)12544 * 1536];  // gathered samples, bf16 hi
__device__ __nv_bfloat16 g_Blo[(size_t)12544 * 1536];  // bf16 lo (residual)
__device__ __nv_bfloat16 g_Ahi[(size_t)768 * 1536];    // dcn_w bf16 hi
__device__ __nv_bfloat16 g_Alo[(size_t)768 * 1536];    // dcn_w bf16 lo

__device__ __forceinline__ float lrelu(float x) { return x >= 0.f ? x : SLOPE * x; }

__device__ __forceinline__ uint32_t smem_to_u32(const void* p) {
    uint32_t a;
    asm("{ .reg .u64 t; cvta.to.shared.u64 t, %1; cvt.u32.u64 %0, t; }" : "=r"(a) : "l"(p));
    return a;
}
__device__ __forceinline__ void cp16(uint32_t dst, const void* src) {
    asm volatile("cp.async.cg.shared.global [%0], [%1], 16;" :: "r"(dst), "l"(src));
}
#define CP_COMMIT() asm volatile("cp.async.commit_group;" ::: "memory")
#define CP_WAIT0()  asm volatile("cp.async.wait_group 0;" ::: "memory")

__device__ __forceinline__ void ldsm4(uint32_t* r, uint32_t addr) {
    asm volatile("ldmatrix.sync.aligned.m8n8.x4.shared.b16 {%0,%1,%2,%3}, [%4];"
                 : "=r"(r[0]), "=r"(r[1]), "=r"(r[2]), "=r"(r[3]) : "r"(addr));
}
__device__ __forceinline__ void mma16816(float* c, const uint32_t* a, uint32_t b0, uint32_t b1) {
    asm volatile(
        "mma.sync.aligned.m16n8k16.row.col.f32.bf16.bf16.f32 "
        "{%0,%1,%2,%3}, {%4,%5,%6,%7}, {%8,%9}, {%0,%1,%2,%3};"
        : "+f"(c[0]), "+f"(c[1]), "+f"(c[2]), "+f"(c[3])
        : "r"(a[0]), "r"(a[1]), "r"(a[2]), "r"(a[3]), "r"(b0), "r"(b1));
}

// =====================================================================================
// K1: stem conv (4x4 stride4) + BN1 + leaky ReLU
// =====================================================================================
__global__ __launch_bounds__(256) void stem_kernel(
    const float* __restrict__ x, const float* __restrict__ sw, const float* __restrict__ sb,
    const float* __restrict__ bg, const float* __restrict__ bb, const float* __restrict__ bm,
    const float* __restrict__ bv)
{
    __shared__ float wst[48][96];
    __shared__ float s_sc[96];
    __shared__ float s_bb[96];

    int tid = threadIdx.x;
    for (int i = tid; i < 96; i += 256) {
        float sc = bg[i] * rsqrtf(bv[i] + EPSV);
        s_sc[i] = sc;
        s_bb[i] = sb[i] * sc + bb[i] - bm[i] * sc;
    }
    __syncthreads();
    for (int i = tid; i < 96 * 48; i += 256) {
        int co = i / 48, k = i % 48;
        wst[k][co] = sw[i] * s_sc[co];
    }
    __syncthreads();

    int b = blockIdx.x / 49;
    int s = (blockIdx.x % 49) * 64 + (tid & 63);
    int quarter = tid >> 6;
    int oh = s / 56, ow = s % 56;

    float patch[48];
    const float* xb = x + (size_t)b * 3 * 224 * 224;
#pragma unroll
    for (int ci = 0; ci < 3; ci++)
#pragma unroll
        for (int r = 0; r < 4; r++) {
            float4 p4 = *(const float4*)(xb + ((size_t)ci * 224 + oh * 4 + r) * 224 + ow * 4);
            patch[ci * 16 + r * 4 + 0] = p4.x;
            patch[ci * 16 + r * 4 + 1] = p4.y;
            patch[ci * 16 + r * 4 + 2] = p4.z;
            patch[ci * 16 + r * 4 + 3] = p4.w;
        }

    float* hb = g_h + (size_t)b * 96 * 3136 + s;
#pragma unroll
    for (int gq = 0; gq < 6; gq++) {
        int co = quarter * 24 + gq * 4;
        float a0 = s_bb[co], a1 = s_bb[co + 1], a2 = s_bb[co + 2], a3 = s_bb[co + 3];
#pragma unroll
        for (int k = 0; k < 48; k++) {
            float4 w4 = *(const float4*)&wst[k][co];
            float pv = patch[k];
            a0 += pv * w4.x; a1 += pv * w4.y; a2 += pv * w4.z; a3 += pv * w4.w;
        }
        hb[(size_t)(co + 0) * 3136] = lrelu(a0);
        hb[(size_t)(co + 1) * 3136] = lrelu(a1);
        hb[(size_t)(co + 2) * 3136] = lrelu(a2);
        hb[(size_t)(co + 3) * 3136] = lrelu(a3);
    }
}

// =====================================================================================
// K2: offset conv (96->32, 4x4 stride4)
// =====================================================================================
__global__ __launch_bounds__(256) void offconv_kernel(
    const float* __restrict__ w_, const float* __restrict__ b_)
{
    __shared__ float patch[1536];
    int bp = blockIdx.x;
    int b = bp / 196, p = bp % 196;
    int oh = p / 14, ow = p % 14;
    int tid = threadIdx.x;

    for (int e = tid; e < 1536; e += 256) {
        int c = e >> 4, r = (e >> 2) & 3, cc = e & 3;
        patch[e] = g_h[(((size_t)b * 96 + c) * 56 + oh * 4 + r) * 56 + ow * 4 + cc];
    }
    __syncthreads();

    int warp = tid >> 5, lane = tid & 31;
#pragma unroll
    for (int q = 0; q < 4; q++) {
        int co = warp * 4 + q;
        const float* w = w_ + (size_t)co * 1536;
        float s = 0.f;
#pragma unroll 8
        for (int k = lane; k < 1536; k += 32) s += patch[k] * w[k];
#pragma unroll
        for (int o = 16; o; o >>= 1) s += __shfl_down_sync(0xffffffffu, s, o);
        if (lane == 0)
            g_off[(((size_t)b * 32 + co) * 14 + oh) * 14 + ow] = s + b_[co];
    }
}

// =====================================================================================
// K3a: bilinear gather -> split bf16 B matrices (hi + residual lo)
// =====================================================================================
__global__ __launch_bounds__(256) void gather_kernel()
{
    __shared__ float s_wy[16], s_wx[16];
    __shared__ int   s_y0[16], s_x0[16];

    int bp = blockIdx.x;
    int b = bp / 196, p = bp % 196;
    int oh = p / 14, ow = p % 14;
    int tid = threadIdx.x;

    if (tid < 16) {
        int kk = tid;
        float o0 = g_off[(((size_t)b * 32 + 2 * kk + 0) * 14 + oh) * 14 + ow];
        float o1 = g_off[(((size_t)b * 32 + 2 * kk + 1) * 14 + oh) * 14 + ow];
        float py = (float)(oh * 4 + (kk >> 2)) + o0;
        float px = (float)(ow * 4 + (kk & 3)) + o1;
        float y0f = floorf(py), x0f = floorf(px);
        s_y0[kk] = (int)y0f; s_x0[kk] = (int)x0f;
        s_wy[kk] = py - y0f; s_wx[kk] = px - x0f;
    }
    __syncthreads();

    const float* hb = g_h + (size_t)b * 96 * 3136;
    size_t rowoff = (size_t)bp * 1536;

    for (int e = tid; e < 1536; e += 256) {
        int c = e >> 4, kk = e & 15;
        int y0 = s_y0[kk], x0 = s_x0[kk];
        float wy = s_wy[kk], wx = s_wx[kk];
        const float* hc = hb + (size_t)c * 3136;

        int y1 = y0 + 1, x1 = x0 + 1;
        bool vy0 = (y0 >= 0) & (y0 < 56), vy1 = (y1 >= 0) & (y1 < 56);
        bool vx0 = (x0 >= 0) & (x0 < 56), vx1 = (x1 >= 0) & (x1 < 56);
        int yc0 = min(max(y0, 0), 55), yc1 = min(max(y1, 0), 55);
        int xc0 = min(max(x0, 0), 55), xc1 = min(max(x1, 0), 55);

        float v00 = (vy0 & vx0) ? hc[yc0 * 56 + xc0] : 0.f;
        float v01 = (vy0 & vx1) ? hc[yc0 * 56 + xc1] : 0.f;
        float v10 = (vy1 & vx0) ? hc[yc1 * 56 + xc0] : 0.f;
        float v11 = (vy1 & vx1) ? hc[yc1 * 56 + xc1] : 0.f;

        float v = v00 * (1.f - wy) * (1.f - wx) + v01 * (1.f - wy) * wx
                + v10 * wy * (1.f - wx)        + v11 * wy * wx;

        __nv_bfloat16 hi = __float2bfloat16(v);
        g_Bhi[rowoff + e] = hi;
        g_Blo[rowoff + e] = __float2bfloat16(v - __bfloat162float(hi));
    }
}

// =====================================================================================
// K3w: split dcn_w into bf16 hi/lo
// =====================================================================================
__global__ __launch_bounds__(256) void convw_kernel(const float* __restrict__ w)
{
    size_t i = (size_t)blockIdx.x * 256 + threadIdx.x;
    if (i < (size_t)768 * 1536) {
        float v = w[i];
        __nv_bfloat16 hi = __float2bfloat16(v);
        g_Ahi[i] = hi;
        g_Alo[i] = __float2bfloat16(v - __bfloat162float(hi));
    }
}

// =====================================================================================
// K3b: split-bf16 tensor-core GEMM via mma.sync (legacy HMMA path; no sm_103a features)
// C[o][n] = A[o][:]·B[n][:], M=768, N=12544, K=1536, products hh+hl+lh.
// CTA tile 128x128, BK=64 (SW128 swizzle), cp.async double-buffered; 8 warps m64n32.
// Epilogue: BN2 + bias + lrelu, transpose via smem, coalesced float4 stores.
// =====================================================================================
#define BK          64
#define NKB         24
#define STAGE       65536
#define S_AHI       0
#define S_ALO       16384
#define S_BHI       32768
#define S_BLO       49152
#define SMEM_TOTAL  (2 * STAGE)

__global__ __launch_bounds__(256, 1) void dcn_mma_kernel(
    const float* __restrict__ db,
    const float* __restrict__ bg, const float* __restrict__ bb,
    const float* __restrict__ bm, const float* __restrict__ bv,
    float* __restrict__ out)
{
    extern __shared__ char smem[];
    __shared__ float s_sc[128], s_sh[128];

    const uint32_t smem_u = smem_to_u32(smem);
    const int tid = threadIdx.x, lane = tid & 31, wid = tid >> 5;
    const int wm = wid >> 2, wn = wid & 3;             // 2 x 4 warp grid
    const int obase = blockIdx.x * 128;                // x fastest: 6 M-tiles share B in L2
    const int nbase = blockIdx.y * 128;

    for (int i = tid; i < 128; i += 256) {
        int o = obase + i;
        float s = bg[o] * rsqrtf(bv[o] + EPSV);
        s_sc[i] = s;
        s_sh[i] = db[o] * s + bb[o] - bm[o] * s;
    }

    // per-thread gmem/smem offsets for stage loads (4 iters x 4 tensors)
    int lr[4], lkc[4];
    uint32_t lso[4];
#pragma unroll
    for (int it = 0; it < 4; it++) {
        int c = tid + it * 256;
        lr[it] = c >> 3; lkc[it] = c & 7;
        uint32_t so = (uint32_t)(lr[it] * 128 + lkc[it] * 16);
        lso[it] = so ^ ((so >> 3) & 0x70);
    }

    float acc[4][4][4];
#pragma unroll
    for (int i = 0; i < 4; i++)
#pragma unroll
        for (int j = 0; j < 4; j++)
#pragma unroll
            for (int q = 0; q < 4; q++) acc[i][j][q] = 0.f;

    // ---- issue stage 0 ----
    {
        uint32_t sb = smem_u;
#pragma unroll
        for (int it = 0; it < 4; it++) {
            size_t ga = (size_t)(obase + lr[it]) * 1536 + lkc[it] * 8;
            size_t gb = (size_t)(nbase + lr[it]) * 1536 + lkc[it] * 8;
            cp16(sb + S_AHI + lso[it], g_Ahi + ga);
            cp16(sb + S_ALO + lso[it], g_Alo + ga);
            cp16(sb + S_BHI + lso[it], g_Bhi + gb);
            cp16(sb + S_BLO + lso[it], g_Blo + gb);
        }
        CP_COMMIT();
    }

    for (int kb = 0; kb < NKB; kb++) {
        CP_WAIT0();
        __syncthreads();

        if (kb + 1 < NKB) {
            uint32_t sb = smem_u + ((kb + 1) & 1) * STAGE;
            int k0 = (kb + 1) * BK;
#pragma unroll
            for (int it = 0; it < 4; it++) {
                size_t ga = (size_t)(obase + lr[it]) * 1536 + k0 + lkc[it] * 8;
                size_t gb = (size_t)(nbase + lr[it]) * 1536 + k0 + lkc[it] * 8;
                cp16(sb + S_AHI + lso[it], g_Ahi + ga);
                cp16(sb + S_ALO + lso[it], g_Alo + ga);
                cp16(sb + S_BHI + lso[it], g_Bhi + gb);
                cp16(sb + S_BLO + lso[it], g_Blo + gb);
            }
        }
        CP_COMMIT();

        const uint32_t cb = smem_u + (kb & 1) * STAGE;
#pragma unroll
        for (int k16 = 0; k16 < 4; k16++) {
            uint32_t a_hi[4][4], a_lo[4][4], b_hi[2][4], b_lo[2][4];
            // A fragments: mat order (m0-7,k0-7),(m8-15,k0-7),(m0-7,k8-15),(m8-15,k8-15)
            {
                int chunk = k16 * 2 + (lane >> 4);
#pragma unroll
                for (int i = 0; i < 4; i++) {
                    int row = wm * 64 + i * 16 + (lane & 15);
                    uint32_t so = (uint32_t)(row * 128 + chunk * 16);
                    so ^= ((so >> 3) & 0x70);
                    ldsm4(a_hi[i], cb + S_AHI + so);
                    ldsm4(a_lo[i], cb + S_ALO + so);
                }
            }
            // B fragments: x4 covers two n8 tiles (khalf interleaved)
            {
                int g = lane >> 3;
#pragma unroll
                for (int t = 0; t < 2; t++) {
                    int row = wn * 32 + (t * 2 + (g >> 1)) * 8 + (lane & 7);
                    int chunk = k16 * 2 + (g & 1);
                    uint32_t so = (uint32_t)(row * 128 + chunk * 16);
                    so ^= ((so >> 3) & 0x70);
                    ldsm4(b_hi[t], cb + S_BHI + so);
                    ldsm4(b_lo[t], cb + S_BLO + so);
                }
            }
#pragma unroll
            for (int i = 0; i < 4; i++)
#pragma unroll
                for (int j = 0; j < 4; j++) {
                    int t = j >> 1, pr = (j & 1) * 2;
                    mma16816(acc[i][j], a_hi[i], b_hi[t][pr], b_hi[t][pr + 1]);
                    mma16816(acc[i][j], a_hi[i], b_lo[t][pr], b_lo[t][pr + 1]);
                    mma16816(acc[i][j], a_lo[i], b_hi[t][pr], b_hi[t][pr + 1]);
                }
        }
        __syncthreads();
    }

    // ---- epilogue: C -> smem (n-major, o contiguous, pad 132) -> BN+lrelu -> out ----
    float* Csm = (float*)smem;
#pragma unroll
    for (int i = 0; i < 4; i++)
#pragma unroll
        for (int j = 0; j < 4; j++) {
            int nl = wn * 32 + j * 8 + 2 * (lane & 3);
            int ol = wm * 64 + i * 16 + (lane >> 2);
            Csm[(size_t)nl * 132 + ol]            = acc[i][j][0];
            Csm[(size_t)(nl + 1) * 132 + ol]      = acc[i][j][1];
            Csm[(size_t)nl * 132 + ol + 8]        = acc[i][j][2];
            Csm[(size_t)(nl + 1) * 132 + ol + 8]  = acc[i][j][3];
        }
    __syncthreads();

    for (int idx = tid; idx < 128 * 32; idx += 256) {
        int nl = idx >> 5, o4 = (idx & 31) * 4;
        float4 v = *(const float4*)&Csm[(size_t)nl * 132 + o4];
        v.x = lrelu(v.x * s_sc[o4 + 0] + s_sh[o4 + 0]);
        v.y = lrelu(v.y * s_sc[o4 + 1] + s_sh[o4 + 1]);
        v.z = lrelu(v.z * s_sc[o4 + 2] + s_sh[o4 + 2]);
        v.w = lrelu(v.w * s_sc[o4 + 3] + s_sh[o4 + 3]);
        *(float4*)&out[(size_t)(nbase + nl) * 768 + obase + o4] = v;
    }
}

// =====================================================================================
extern "C" void kernel_launch(void* const* d_in, const int* in_sizes, int n_in,
                              void* d_out, int out_size)
{
    const float* x      = (const float*)d_in[0];
    const float* stem_w = (const float*)d_in[1];
    const float* stem_b = (const float*)d_in[2];
    const float* bn1_g  = (const float*)d_in[3];
    const float* bn1_b  = (const float*)d_in[4];
    const float* bn1_m  = (const float*)d_in[5];
    const float* bn1_v  = (const float*)d_in[6];
    const float* off_w  = (const float*)d_in[7];
    const float* off_b  = (const float*)d_in[8];
    const float* dcn_w  = (const float*)d_in[9];
    const float* dcn_b  = (const float*)d_in[10];
    const float* bn2_g  = (const float*)d_in[11];
    const float* bn2_b  = (const float*)d_in[12];
    const float* bn2_m  = (const float*)d_in[13];
    const float* bn2_v  = (const float*)d_in[14];
    float* out = (float*)d_out;

    cudaFuncSetAttribute(dcn_mma_kernel, cudaFuncAttributeMaxDynamicSharedMemorySize, SMEM_TOTAL);

    stem_kernel<<<64 * 49, 256>>>(x, stem_w, stem_b, bn1_g, bn1_b, bn1_m, bn1_v);
    convw_kernel<<<(768 * 1536 + 255) / 256, 256>>>(dcn_w);
    offconv_kernel<<<64 * 196, 256>>>(off_w, off_b);
    gather_kernel<<<64 * 196, 256>>>();
    dcn_mma_kernel<<<dim3(6, 98), 256, SMEM_TOTAL>>>(dcn_b, bn2_g, bn2_b, bn2_m, bn2_v, out);
}

// round 9
// speedup vs baseline: 2.2316x; 1.1679x over previous
#include <cuda_runtime.h>
#include <cuda_bf16.h>
#include <cstdint>

#define EPSV  1e-5f
#define SLOPE 0.01f

// ---------------- scratch (static device memory; no allocs allowed) ----------------
__device__ float g_h[(size_t)64 * 56 * 56 * 96];       // stem output, CHANNEL-LAST [b][y][x][c]
__device__ float g_off[(size_t)64 * 32 * 14 * 14];     // offsets
__device__ float g_offw[32 * 1536];                    // off_w permuted [kk][c][co]
__device__ __nv_bfloat16 g_Bhi[(size_t)12544 * 1536];  // gathered samples, bf16 hi (k = kk*96+c)
__device__ __nv_bfloat16 g_Blo[(size_t)12544 * 1536];  // bf16 lo (residual)
__device__ __nv_bfloat16 g_Ahi[(size_t)768 * 1536];    // dcn_w bf16 hi (k = kk*96+c)
__device__ __nv_bfloat16 g_Alo[(size_t)768 * 1536];    // bf16 lo

__device__ __forceinline__ float lrelu(float x) { return x >= 0.f ? x : SLOPE * x; }

__device__ __forceinline__ uint32_t smem_to_u32(const void* p) {
    uint32_t a;
    asm("{ .reg .u64 t; cvta.to.shared.u64 t, %1; cvt.u32.u64 %0, t; }" : "=r"(a) : "l"(p));
    return a;
}
__device__ __forceinline__ void cp16(uint32_t dst, const void* src) {
    asm volatile("cp.async.cg.shared.global [%0], [%1], 16;" :: "r"(dst), "l"(src));
}
#define CP_COMMIT() asm volatile("cp.async.commit_group;" ::: "memory")
#define CP_WAIT0()  asm volatile("cp.async.wait_group 0;" ::: "memory")

__device__ __forceinline__ void ldsm4(uint32_t* r, uint32_t addr) {
    asm volatile("ldmatrix.sync.aligned.m8n8.x4.shared.b16 {%0,%1,%2,%3}, [%4];"
                 : "=r"(r[0]), "=r"(r[1]), "=r"(r[2]), "=r"(r[3]) : "r"(addr));
}
__device__ __forceinline__ void mma16816(float* c, const uint32_t* a, uint32_t b0, uint32_t b1) {
    asm volatile(
        "mma.sync.aligned.m16n8k16.row.col.f32.bf16.bf16.f32 "
        "{%0,%1,%2,%3}, {%4,%5,%6,%7}, {%8,%9}, {%0,%1,%2,%3};"
        : "+f"(c[0]), "+f"(c[1]), "+f"(c[2]), "+f"(c[3])
        : "r"(a[0]), "r"(a[1]), "r"(a[2]), "r"(a[3]), "r"(b0), "r"(b1));
}

// packed f32x2 helpers
__device__ __forceinline__ unsigned long long pk2(float x, float y) {
    unsigned long long r;
    asm("mov.b64 %0,{%1,%2};" : "=l"(r) : "f"(x), "f"(y));
    return r;
}
__device__ __forceinline__ unsigned long long fma2(unsigned long long a,
                                                   unsigned long long b,
                                                   unsigned long long c) {
    unsigned long long d;
    asm("fma.rn.f32x2 %0,%1,%2,%3;" : "=l"(d) : "l"(a), "l"(b), "l"(c));
    return d;
}
__device__ __forceinline__ void upk2(unsigned long long v, float& lo, float& hi) {
    asm("mov.b64 {%0,%1},%2;" : "=f"(lo), "=f"(hi) : "l"(v));
}

// =====================================================================================
// K1: stem conv (4x4 stride4) + BN1 + leaky ReLU, f32x2 accumulation,
// channel-last output via smem transpose (coalesced 384B store groups).
// =====================================================================================
__global__ __launch_bounds__(256) void stem_kernel(
    const float* __restrict__ x, const float* __restrict__ sw, const float* __restrict__ sb,
    const float* __restrict__ bg, const float* __restrict__ bb, const float* __restrict__ bm,
    const float* __restrict__ bv)
{
    __shared__ float wst[48][96];
    __shared__ float s_bb[96];
    __shared__ float s_sc[96];
    __shared__ float hout[64][100];   // padded: conflict-free STS.128

    int tid = threadIdx.x;
    for (int i = tid; i < 96; i += 256) {
        float sc = bg[i] * rsqrtf(bv[i] + EPSV);
        s_sc[i] = sc;
        s_bb[i] = sb[i] * sc + bb[i] - bm[i] * sc;
    }
    __syncthreads();
    for (int i = tid; i < 96 * 48; i += 256) {
        int co = i / 48, k = i % 48;
        wst[k][co] = sw[i] * s_sc[co];
    }
    __syncthreads();

    int b = blockIdx.x / 49;
    int sblk = (blockIdx.x % 49) * 64;
    int sl = tid & 63;
    int s = sblk + sl;
    int quarter = tid >> 6;
    int oh = s / 56, ow = s % 56;

    float patch[48];
    const float* xb = x + (size_t)b * 3 * 224 * 224;
#pragma unroll
    for (int ci = 0; ci < 3; ci++)
#pragma unroll
        for (int r = 0; r < 4; r++) {
            float4 p4 = *(const float4*)(xb + ((size_t)ci * 224 + oh * 4 + r) * 224 + ow * 4);
            patch[ci * 16 + r * 4 + 0] = p4.x;
            patch[ci * 16 + r * 4 + 1] = p4.y;
            patch[ci * 16 + r * 4 + 2] = p4.z;
            patch[ci * 16 + r * 4 + 3] = p4.w;
        }

#pragma unroll
    for (int gq = 0; gq < 6; gq++) {
        int co = quarter * 24 + gq * 4;
        unsigned long long a01 = pk2(s_bb[co], s_bb[co + 1]);
        unsigned long long a23 = pk2(s_bb[co + 2], s_bb[co + 3]);
#pragma unroll
        for (int k = 0; k < 48; k++) {
            float4 w4 = *(const float4*)&wst[k][co];
            unsigned long long pv2 = pk2(patch[k], patch[k]);
            a01 = fma2(pv2, pk2(w4.x, w4.y), a01);
            a23 = fma2(pv2, pk2(w4.z, w4.w), a23);
        }
        float t0, t1, t2, t3;
        upk2(a01, t0, t1); upk2(a23, t2, t3);
        float4 v;
        v.x = lrelu(t0); v.y = lrelu(t1); v.z = lrelu(t2); v.w = lrelu(t3);
        *(float4*)&hout[sl][co] = v;
    }
    __syncthreads();

    float* hb = g_h + ((size_t)b * 3136 + sblk) * 96;
    for (int e = tid; e < 64 * 24; e += 256) {
        int slo = e / 24, c4 = e % 24;
        *(float4*)(hb + (size_t)slo * 96 + c4 * 4) = *(const float4*)&hout[slo][c4 * 4];
    }
}

// =====================================================================================
// K1b: permute off_w -> g_offw[kk][c][co]
// =====================================================================================
__global__ __launch_bounds__(256) void offw_perm_kernel(const float* __restrict__ w)
{
    int i = blockIdx.x * 256 + threadIdx.x;
    if (i < 32 * 1536) {
        int kk = i / 3072, r = i % 3072, c = r / 32, co = r & 31;
        g_offw[i] = w[(size_t)co * 1536 + c * 16 + kk];
    }
}

// =====================================================================================
// K2: offset conv as tiled GEMM. Off[32, 12544] = W[32,1536] · P[1536, 12544],
// K-order kk*96+c (P column = contiguous 96 ch of h at the tap position).
// Block: 128 positions; BK=96 (one kk); f32x2 compute; fp32-exact.
// =====================================================================================
#define OC_SMEM ((96 * 128 + 96 * 32) * 4)
__global__ __launch_bounds__(256) void offconv_kernel(const float* __restrict__ b_)
{
    extern __shared__ float sm[];
    float* Pt = sm;             // [96][128] k-major
    float* Wt = sm + 96 * 128;  // [96][32]  k-major

    int tid = threadIdx.x;
    int nbase = blockIdx.x * 128;
    int tx = tid & 31, ty = tid >> 5;   // tx: 4-n group, ty: 4-co group

    unsigned long long acc2[4][2];
#pragma unroll
    for (int i = 0; i < 4; i++) { acc2[i][0] = 0ull; acc2[i][1] = 0ull; }

    for (int kb = 0; kb < 16; kb++) {
        int kh = kb >> 2, kw = kb & 3;
        for (int e = tid; e < 3072; e += 256)          // Wt[c][co] <- g_offw coalesced
            Wt[e] = g_offw[kb * 3072 + e];
        for (int e = tid; e < 3072; e += 256) {        // Pt[k][ni]
            int c4 = e >> 7, ni = e & 127;
            int n = nbase + ni, b = n / 196, p = n % 196;
            int oh = p / 14, ow = p % 14;
            float4 v = *(const float4*)(g_h +
                ((size_t)b * 3136 + (oh * 4 + kh) * 56 + ow * 4 + kw) * 96 + c4 * 4);
            int k0 = c4 * 4;
            Pt[(k0 + 0) * 128 + ni] = v.x;
            Pt[(k0 + 1) * 128 + ni] = v.y;
            Pt[(k0 + 2) * 128 + ni] = v.z;
            Pt[(k0 + 3) * 128 + ni] = v.w;
        }
        __syncthreads();

#pragma unroll 4
        for (int k = 0; k < 96; k++) {
            float4 wv = *(const float4*)&Wt[k * 32 + ty * 4];
            float4 pv = *(const float4*)&Pt[k * 128 + tx * 4];
            unsigned long long p01 = pk2(pv.x, pv.y), p23 = pk2(pv.z, pv.w);
            acc2[0][0] = fma2(pk2(wv.x, wv.x), p01, acc2[0][0]);
            acc2[0][1] = fma2(pk2(wv.x, wv.x), p23, acc2[0][1]);
            acc2[1][0] = fma2(pk2(wv.y, wv.y), p01, acc2[1][0]);
            acc2[1][1] = fma2(pk2(wv.y, wv.y), p23, acc2[1][1]);
            acc2[2][0] = fma2(pk2(wv.z, wv.z), p01, acc2[2][0]);
            acc2[2][1] = fma2(pk2(wv.z, wv.z), p23, acc2[2][1]);
            acc2[3][0] = fma2(pk2(wv.w, wv.w), p01, acc2[3][0]);
            acc2[3][1] = fma2(pk2(wv.w, wv.w), p23, acc2[3][1]);
        }
        __syncthreads();
    }

#pragma unroll
    for (int i = 0; i < 4; i++) {
        int co = ty * 4 + i;
        float bias = b_[co];
        float v[4];
        upk2(acc2[i][0], v[0], v[1]);
        upk2(acc2[i][1], v[2], v[3]);
#pragma unroll
        for (int j = 0; j < 4; j++) {
            int n = nbase + tx * 4 + j;
            int b = n / 196, p = n % 196, oh = p / 14, ow = p % 14;
            g_off[(((size_t)b * 32 + co) * 14 + oh) * 14 + ow] = v[j] + bias;
        }
    }
}

// =====================================================================================
// K3a: bilinear gather -> split bf16 B (k = kk*96+c). 384 threads = (kk, c4) grid;
// each thread: 4 channels x 4 taps as float4 loads (coalesced 384B per kk-group).
// =====================================================================================
__global__ __launch_bounds__(384) void gather_kernel()
{
    __shared__ float s_wy[16], s_wx[16];
    __shared__ int   s_y0[16], s_x0[16];

    int bp = blockIdx.x;
    int b = bp / 196, p = bp % 196;
    int oh = p / 14, ow = p % 14;
    int tid = threadIdx.x;

    if (tid < 16) {
        int kk = tid;
        float o0 = g_off[(((size_t)b * 32 + 2 * kk + 0) * 14 + oh) * 14 + ow];
        float o1 = g_off[(((size_t)b * 32 + 2 * kk + 1) * 14 + oh) * 14 + ow];
        float py = (float)(oh * 4 + (kk >> 2)) + o0;
        float px = (float)(ow * 4 + (kk & 3)) + o1;
        float y0f = floorf(py), x0f = floorf(px);
        s_y0[kk] = (int)y0f; s_x0[kk] = (int)x0f;
        s_wy[kk] = py - y0f; s_wx[kk] = px - x0f;
    }
    __syncthreads();

    int kk = tid / 24, c4 = tid % 24;
    int y0 = s_y0[kk], x0 = s_x0[kk];
    float wy = s_wy[kk], wx = s_wx[kk];
    int y1 = y0 + 1, x1 = x0 + 1;
    bool vy0 = (y0 >= 0) & (y0 < 56), vy1 = (y1 >= 0) & (y1 < 56);
    bool vx0 = (x0 >= 0) & (x0 < 56), vx1 = (x1 >= 0) & (x1 < 56);
    int yc0 = min(max(y0, 0), 55), yc1 = min(max(y1, 0), 55);
    int xc0 = min(max(x0, 0), 55), xc1 = min(max(x1, 0), 55);

    const float* hb = g_h + (size_t)b * 3136 * 96 + c4 * 4;
    const float4 z = make_float4(0.f, 0.f, 0.f, 0.f);
    float4 v00 = (vy0 & vx0) ? *(const float4*)(hb + ((size_t)yc0 * 56 + xc0) * 96) : z;
    float4 v01 = (vy0 & vx1) ? *(const float4*)(hb + ((size_t)yc0 * 56 + xc1) * 96) : z;
    float4 v10 = (vy1 & vx0) ? *(const float4*)(hb + ((size_t)yc1 * 56 + xc0) * 96) : z;
    float4 v11 = (vy1 & vx1) ? *(const float4*)(hb + ((size_t)yc1 * 56 + xc1) * 96) : z;

    float w00 = (1.f - wy) * (1.f - wx), w01 = (1.f - wy) * wx;
    float w10 = wy * (1.f - wx),         w11 = wy * wx;

    float r[4];
    r[0] = v00.x * w00 + v01.x * w01 + v10.x * w10 + v11.x * w11;
    r[1] = v00.y * w00 + v01.y * w01 + v10.y * w10 + v11.y * w11;
    r[2] = v00.z * w00 + v01.z * w01 + v10.z * w10 + v11.z * w11;
    r[3] = v00.w * w00 + v01.w * w01 + v10.w * w10 + v11.w * w11;

    size_t idx = (size_t)bp * 1536 + kk * 96 + c4 * 4;
    __nv_bfloat16 h0 = __float2bfloat16(r[0]);
    __nv_bfloat16 h1 = __float2bfloat16(r[1]);
    __nv_bfloat16 h2 = __float2bfloat16(r[2]);
    __nv_bfloat16 h3 = __float2bfloat16(r[3]);
    *(__nv_bfloat162*)(g_Bhi + idx)     = __halves2bfloat162(h0, h1);
    *(__nv_bfloat162*)(g_Bhi + idx + 2) = __halves2bfloat162(h2, h3);
    *(__nv_bfloat162*)(g_Blo + idx) = __halves2bfloat162(
        __float2bfloat16(r[0] - __bfloat162float(h0)),
        __float2bfloat16(r[1] - __bfloat162float(h1)));
    *(__nv_bfloat162*)(g_Blo + idx + 2) = __halves2bfloat162(
        __float2bfloat16(r[2] - __bfloat162float(h2)),
        __float2bfloat16(r[3] - __bfloat162float(h3)));
}

// =====================================================================================
// K3w: split + permute dcn_w -> g_Ahi/g_Alo with k = kk*96+c
// =====================================================================================
__global__ __launch_bounds__(256) void convw_kernel(const float* __restrict__ w)
{
    size_t i = (size_t)blockIdx.x * 256 + threadIdx.x;
    if (i < (size_t)768 * 1536) {
        int o = (int)(i / 1536), r = (int)(i % 1536);
        int kk = r / 96, c = r % 96;
        float v = w[(size_t)o * 1536 + c * 16 + kk];
        __nv_bfloat16 hi = __float2bfloat16(v);
        g_Ahi[i] = hi;
        g_Alo[i] = __float2bfloat16(v - __bfloat162float(hi));
    }
}

// =====================================================================================
// K3b: split-bf16 tensor-core GEMM via mma.sync (unchanged from R8 — proven)
// =====================================================================================
#define BK          64
#define NKB         24
#define STAGE       65536
#define S_AHI       0
#define S_ALO       16384
#define S_BHI       32768
#define S_BLO       49152
#define SMEM_TOTAL  (2 * STAGE)

__global__ __launch_bounds__(256, 1) void dcn_mma_kernel(
    const float* __restrict__ db,
    const float* __restrict__ bg, const float* __restrict__ bb,
    const float* __restrict__ bm, const float* __restrict__ bv,
    float* __restrict__ out)
{
    extern __shared__ char smem[];
    __shared__ float s_sc[128], s_sh[128];

    const uint32_t smem_u = smem_to_u32(smem);
    const int tid = threadIdx.x, lane = tid & 31, wid = tid >> 5;
    const int wm = wid >> 2, wn = wid & 3;
    const int obase = blockIdx.x * 128;
    const int nbase = blockIdx.y * 128;

    for (int i = tid; i < 128; i += 256) {
        int o = obase + i;
        float s = bg[o] * rsqrtf(bv[o] + EPSV);
        s_sc[i] = s;
        s_sh[i] = db[o] * s + bb[o] - bm[o] * s;
    }

    int lr[4], lkc[4];
    uint32_t lso[4];
#pragma unroll
    for (int it = 0; it < 4; it++) {
        int c = tid + it * 256;
        lr[it] = c >> 3; lkc[it] = c & 7;
        uint32_t so = (uint32_t)(lr[it] * 128 + lkc[it] * 16);
        lso[it] = so ^ ((so >> 3) & 0x70);
    }

    float acc[4][4][4];
#pragma unroll
    for (int i = 0; i < 4; i++)
#pragma unroll
        for (int j = 0; j < 4; j++)
#pragma unroll
            for (int q = 0; q < 4; q++) acc[i][j][q] = 0.f;

    {
        uint32_t sb = smem_u;
#pragma unroll
        for (int it = 0; it < 4; it++) {
            size_t ga = (size_t)(obase + lr[it]) * 1536 + lkc[it] * 8;
            size_t gb = (size_t)(nbase + lr[it]) * 1536 + lkc[it] * 8;
            cp16(sb + S_AHI + lso[it], g_Ahi + ga);
            cp16(sb + S_ALO + lso[it], g_Alo + ga);
            cp16(sb + S_BHI + lso[it], g_Bhi + gb);
            cp16(sb + S_BLO + lso[it], g_Blo + gb);
        }
        CP_COMMIT();
    }

    for (int kb = 0; kb < NKB; kb++) {
        CP_WAIT0();
        __syncthreads();

        if (kb + 1 < NKB) {
            uint32_t sb = smem_u + ((kb + 1) & 1) * STAGE;
            int k0 = (kb + 1) * BK;
#pragma unroll
            for (int it = 0; it < 4; it++) {
                size_t ga = (size_t)(obase + lr[it]) * 1536 + k0 + lkc[it] * 8;
                size_t gb = (size_t)(nbase + lr[it]) * 1536 + k0 + lkc[it] * 8;
                cp16(sb + S_AHI + lso[it], g_Ahi + ga);
                cp16(sb + S_ALO + lso[it], g_Alo + ga);
                cp16(sb + S_BHI + lso[it], g_Bhi + gb);
                cp16(sb + S_BLO + lso[it], g_Blo + gb);
            }
        }
        CP_COMMIT();

        const uint32_t cb = smem_u + (kb & 1) * STAGE;
#pragma unroll
        for (int k16 = 0; k16 < 4; k16++) {
            uint32_t a_hi[4][4], a_lo[4][4], b_hi[2][4], b_lo[2][4];
            {
                int chunk = k16 * 2 + (lane >> 4);
#pragma unroll
                for (int i = 0; i < 4; i++) {
                    int row = wm * 64 + i * 16 + (lane & 15);
                    uint32_t so = (uint32_t)(row * 128 + chunk * 16);
                    so ^= ((so >> 3) & 0x70);
                    ldsm4(a_hi[i], cb + S_AHI + so);
                    ldsm4(a_lo[i], cb + S_ALO + so);
                }
            }
            {
                int g = lane >> 3;
#pragma unroll
                for (int t = 0; t < 2; t++) {
                    int row = wn * 32 + (t * 2 + (g >> 1)) * 8 + (lane & 7);
                    int chunk = k16 * 2 + (g & 1);
                    uint32_t so = (uint32_t)(row * 128 + chunk * 16);
                    so ^= ((so >> 3) & 0x70);
                    ldsm4(b_hi[t], cb + S_BHI + so);
                    ldsm4(b_lo[t], cb + S_BLO + so);
                }
            }
#pragma unroll
            for (int i = 0; i < 4; i++)
#pragma unroll
                for (int j = 0; j < 4; j++) {
                    int t = j >> 1, pr = (j & 1) * 2;
                    mma16816(acc[i][j], a_hi[i], b_hi[t][pr], b_hi[t][pr + 1]);
                    mma16816(acc[i][j], a_hi[i], b_lo[t][pr], b_lo[t][pr + 1]);
                    mma16816(acc[i][j], a_lo[i], b_hi[t][pr], b_hi[t][pr + 1]);
                }
        }
        __syncthreads();
    }

    float* Csm = (float*)smem;
#pragma unroll
    for (int i = 0; i < 4; i++)
#pragma unroll
        for (int j = 0; j < 4; j++) {
            int nl = wn * 32 + j * 8 + 2 * (lane & 3);
            int ol = wm * 64 + i * 16 + (lane >> 2);
            Csm[(size_t)nl * 132 + ol]            = acc[i][j][0];
            Csm[(size_t)(nl + 1) * 132 + ol]      = acc[i][j][1];
            Csm[(size_t)nl * 132 + ol + 8]        = acc[i][j][2];
            Csm[(size_t)(nl + 1) * 132 + ol + 8]  = acc[i][j][3];
        }
    __syncthreads();

    for (int idx = tid; idx < 128 * 32; idx += 256) {
        int nl = idx >> 5, o4 = (idx & 31) * 4;
        float4 v = *(const float4*)&Csm[(size_t)nl * 132 + o4];
        v.x = lrelu(v.x * s_sc[o4 + 0] + s_sh[o4 + 0]);
        v.y = lrelu(v.y * s_sc[o4 + 1] + s_sh[o4 + 1]);
        v.z = lrelu(v.z * s_sc[o4 + 2] + s_sh[o4 + 2]);
        v.w = lrelu(v.w * s_sc[o4 + 3] + s_sh[o4 + 3]);
        *(float4*)&out[(size_t)(nbase + nl) * 768 + obase + o4] = v;
    }
}

// =====================================================================================
extern "C" void kernel_launch(void* const* d_in, const int* in_sizes, int n_in,
                              void* d_out, int out_size)
{
    const float* x      = (const float*)d_in[0];
    const float* stem_w = (const float*)d_in[1];
    const float* stem_b = (const float*)d_in[2];
    const float* bn1_g  = (const float*)d_in[3];
    const float* bn1_b  = (const float*)d_in[4];
    const float* bn1_m  = (const float*)d_in[5];
    const float* bn1_v  = (const float*)d_in[6];
    const float* off_w  = (const float*)d_in[7];
    const float* off_b  = (const float*)d_in[8];
    const float* dcn_w  = (const float*)d_in[9];
    const float* dcn_b  = (const float*)d_in[10];
    const float* bn2_g  = (const float*)d_in[11];
    const float* bn2_b  = (const float*)d_in[12];
    const float* bn2_m  = (const float*)d_in[13];
    const float* bn2_v  = (const float*)d_in[14];
    float* out = (float*)d_out;

    cudaFuncSetAttribute(dcn_mma_kernel, cudaFuncAttributeMaxDynamicSharedMemorySize, SMEM_TOTAL);
    cudaFuncSetAttribute(offconv_kernel, cudaFuncAttributeMaxDynamicSharedMemorySize, OC_SMEM);

    stem_kernel<<<64 * 49, 256>>>(x, stem_w, stem_b, bn1_g, bn1_b, bn1_m, bn1_v);
    offw_perm_kernel<<<(32 * 1536 + 255) / 256, 256>>>(off_w);
    convw_kernel<<<(768 * 1536 + 255) / 256, 256>>>(dcn_w);
    offconv_kernel<<<98, 256, OC_SMEM>>>(off_b);
    gather_kernel<<<64 * 196, 384>>>();
    dcn_mma_kernel<<<dim3(6, 98), 256, SMEM_TOTAL>>>(dcn_b, bn2_g, bn2_b, bn2_m, bn2_v, out);
}

// round 11
// speedup vs baseline: 2.4951x; 1.1181x over previous
#include <cuda_runtime.h>
#include <cuda_bf16.h>
#include <cstdint>

#define EPSV  1e-5f
#define SLOPE 0.01f

// ---------------- scratch (static device memory; no allocs allowed) ----------------
__device__ float g_h[(size_t)64 * 56 * 56 * 96];       // stem output, CHANNEL-LAST [b][y][x][c]
__device__ float g_off[(size_t)64 * 32 * 14 * 14];     // offsets
__device__ float g_offw[32 * 1536];                    // off_w permuted [kk][c][co]
__device__ float g_part[(size_t)4 * 32 * 12544];       // offconv K-split partials
__device__ __nv_bfloat16 g_Bhi[(size_t)12544 * 1536];  // gathered samples, bf16 hi (k = kk*96+c)
__device__ __nv_bfloat16 g_Blo[(size_t)12544 * 1536];  // bf16 lo (residual)
__device__ __nv_bfloat16 g_Ahi[(size_t)768 * 1536];    // dcn_w bf16 hi (k = kk*96+c)
__device__ __nv_bfloat16 g_Alo[(size_t)768 * 1536];    // bf16 lo

__device__ __forceinline__ float lrelu(float x) { return x >= 0.f ? x : SLOPE * x; }

__device__ __forceinline__ uint32_t smem_to_u32(const void* p) {
    uint32_t a;
    asm("{ .reg .u64 t; cvta.to.shared.u64 t, %1; cvt.u32.u64 %0, t; }" : "=r"(a) : "l"(p));
    return a;
}
__device__ __forceinline__ void cp16(uint32_t dst, const void* src) {
    asm volatile("cp.async.cg.shared.global [%0], [%1], 16;" :: "r"(dst), "l"(src));
}
#define CP_COMMIT() asm volatile("cp.async.commit_group;" ::: "memory")
#define CP_WAIT0()  asm volatile("cp.async.wait_group 0;" ::: "memory")

__device__ __forceinline__ void ldsm4(uint32_t* r, uint32_t addr) {
    asm volatile("ldmatrix.sync.aligned.m8n8.x4.shared.b16 {%0,%1,%2,%3}, [%4];"
                 : "=r"(r[0]), "=r"(r[1]), "=r"(r[2]), "=r"(r[3]) : "r"(addr));
}
__device__ __forceinline__ void mma16816(float* c, const uint32_t* a, uint32_t b0, uint32_t b1) {
    asm volatile(
        "mma.sync.aligned.m16n8k16.row.col.f32.bf16.bf16.f32 "
        "{%0,%1,%2,%3}, {%4,%5,%6,%7}, {%8,%9}, {%0,%1,%2,%3};"
        : "+f"(c[0]), "+f"(c[1]), "+f"(c[2]), "+f"(c[3])
        : "r"(a[0]), "r"(a[1]), "r"(a[2]), "r"(a[3]), "r"(b0), "r"(b1));
}

// packed f32x2 helpers
__device__ __forceinline__ unsigned long long pk2(float x, float y) {
    unsigned long long r;
    asm("mov.b64 %0,{%1,%2};" : "=l"(r) : "f"(x), "f"(y));
    return r;
}
__device__ __forceinline__ unsigned long long fma2(unsigned long long a,
                                                   unsigned long long b,
                                                   unsigned long long c) {
    unsigned long long d;
    asm("fma.rn.f32x2 %0,%1,%2,%3;" : "=l"(d) : "l"(a), "l"(b), "l"(c));
    return d;
}
__device__ __forceinline__ void upk2(unsigned long long v, float& lo, float& hi) {
    asm("mov.b64 {%0,%1},%2;" : "=f"(lo), "=f"(hi) : "l"(v));
}

// =====================================================================================
// K1: stem conv (4x4 stride4) + BN1 + leaky ReLU, f32x2 accumulation,
// channel-last output via smem transpose (coalesced store groups).
// =====================================================================================
__global__ __launch_bounds__(256) void stem_kernel(
    const float* __restrict__ x, const float* __restrict__ sw, const float* __restrict__ sb,
    const float* __restrict__ bg, const float* __restrict__ bb, const float* __restrict__ bm,
    const float* __restrict__ bv)
{
    __shared__ float wst[48][96];
    __shared__ float s_bb[96];
    __shared__ float s_sc[96];
    __shared__ float hout[64][100];   // padded: conflict-free STS.128

    int tid = threadIdx.x;
    for (int i = tid; i < 96; i += 256) {
        float sc = bg[i] * rsqrtf(bv[i] + EPSV);
        s_sc[i] = sc;
        s_bb[i] = sb[i] * sc + bb[i] - bm[i] * sc;
    }
    __syncthreads();
    for (int i = tid; i < 96 * 48; i += 256) {
        int co = i / 48, k = i % 48;
        wst[k][co] = sw[i] * s_sc[co];
    }
    __syncthreads();

    int b = blockIdx.x / 49;
    int sblk = (blockIdx.x % 49) * 64;
    int sl = tid & 63;
    int s = sblk + sl;
    int quarter = tid >> 6;
    int oh = s / 56, ow = s % 56;

    float patch[48];
    const float* xb = x + (size_t)b * 3 * 224 * 224;
#pragma unroll
    for (int ci = 0; ci < 3; ci++)
#pragma unroll
        for (int r = 0; r < 4; r++) {
            float4 p4 = *(const float4*)(xb + ((size_t)ci * 224 + oh * 4 + r) * 224 + ow * 4);
            patch[ci * 16 + r * 4 + 0] = p4.x;
            patch[ci * 16 + r * 4 + 1] = p4.y;
            patch[ci * 16 + r * 4 + 2] = p4.z;
            patch[ci * 16 + r * 4 + 3] = p4.w;
        }

#pragma unroll
    for (int gq = 0; gq < 6; gq++) {
        int co = quarter * 24 + gq * 4;
        unsigned long long a01 = pk2(s_bb[co], s_bb[co + 1]);
        unsigned long long a23 = pk2(s_bb[co + 2], s_bb[co + 3]);
#pragma unroll
        for (int k = 0; k < 48; k++) {
            float4 w4 = *(const float4*)&wst[k][co];
            unsigned long long pv2 = pk2(patch[k], patch[k]);
            a01 = fma2(pv2, pk2(w4.x, w4.y), a01);
            a23 = fma2(pv2, pk2(w4.z, w4.w), a23);
        }
        float t0, t1, t2, t3;
        upk2(a01, t0, t1); upk2(a23, t2, t3);
        float4 v;
        v.x = lrelu(t0); v.y = lrelu(t1); v.z = lrelu(t2); v.w = lrelu(t3);
        *(float4*)&hout[sl][co] = v;
    }
    __syncthreads();

    float* hb = g_h + ((size_t)b * 3136 + sblk) * 96;
    for (int e = tid; e < 64 * 24; e += 256) {
        int slo = e / 24, c4 = e % 24;
        *(float4*)(hb + (size_t)slo * 96 + c4 * 4) = *(const float4*)&hout[slo][c4 * 4];
    }
}

// =====================================================================================
// K1b: permute off_w -> g_offw[kk][c][co]
// =====================================================================================
__global__ __launch_bounds__(256) void offw_perm_kernel(const float* __restrict__ w)
{
    int i = blockIdx.x * 256 + threadIdx.x;
    if (i < 32 * 1536) {
        int kk = i / 3072, r = i % 3072, c = r / 32, co = r & 31;
        g_offw[i] = w[(size_t)co * 1536 + c * 16 + kk];
    }
}

// =====================================================================================
// K2a: offset conv partial GEMM, K split 4 ways.
// grid (98, 4): block = 128 positions x 4 kk taps -> g_part[g][co][n].
// 392 CTAs, 3 co-resident per SM (61KB smem) -> latency hidden.
// =====================================================================================
#define OC_SMEM ((96 * 128 + 96 * 32) * 4)
__global__ __launch_bounds__(256) void offconv_part_kernel()
{
    extern __shared__ float sm[];
    float* Pt = sm;             // [96][128] k-major
    float* Wt = sm + 96 * 128;  // [96][32]  k-major

    int tid = threadIdx.x;
    int nbase = blockIdx.x * 128;
    int g = blockIdx.y;
    int tx = tid & 31, ty = tid >> 5;   // tx: 4-n group, ty: 4-co group

    unsigned long long acc2[4][2];
#pragma unroll
    for (int i = 0; i < 4; i++) { acc2[i][0] = 0ull; acc2[i][1] = 0ull; }

    for (int kb = g * 4; kb < g * 4 + 4; kb++) {
        int kh = kb >> 2, kw = kb & 3;
        for (int e = tid; e < 3072; e += 256)          // Wt[c][co] <- g_offw coalesced
            Wt[e] = g_offw[kb * 3072 + e];
        for (int e = tid; e < 3072; e += 256) {        // Pt[k][ni]
            int c4 = e >> 7, ni = e & 127;
            int n = nbase + ni, b = n / 196, p = n % 196;
            int oh = p / 14, ow = p % 14;
            float4 v = *(const float4*)(g_h +
                ((size_t)b * 3136 + (oh * 4 + kh) * 56 + ow * 4 + kw) * 96 + c4 * 4);
            int k0 = c4 * 4;
            Pt[(k0 + 0) * 128 + ni] = v.x;
            Pt[(k0 + 1) * 128 + ni] = v.y;
            Pt[(k0 + 2) * 128 + ni] = v.z;
            Pt[(k0 + 3) * 128 + ni] = v.w;
        }
        __syncthreads();

#pragma unroll 4
        for (int k = 0; k < 96; k++) {
            float4 wv = *(const float4*)&Wt[k * 32 + ty * 4];
            float4 pv = *(const float4*)&Pt[k * 128 + tx * 4];
            unsigned long long p01 = pk2(pv.x, pv.y), p23 = pk2(pv.z, pv.w);
            acc2[0][0] = fma2(pk2(wv.x, wv.x), p01, acc2[0][0]);
            acc2[0][1] = fma2(pk2(wv.x, wv.x), p23, acc2[0][1]);
            acc2[1][0] = fma2(pk2(wv.y, wv.y), p01, acc2[1][0]);
            acc2[1][1] = fma2(pk2(wv.y, wv.y), p23, acc2[1][1]);
            acc2[2][0] = fma2(pk2(wv.z, wv.z), p01, acc2[2][0]);
            acc2[2][1] = fma2(pk2(wv.z, wv.z), p23, acc2[2][1]);
            acc2[3][0] = fma2(pk2(wv.w, wv.w), p01, acc2[3][0]);
            acc2[3][1] = fma2(pk2(wv.w, wv.w), p23, acc2[3][1]);
        }
        __syncthreads();
    }

#pragma unroll
    for (int i = 0; i < 4; i++) {
        int co = ty * 4 + i;
        float v[4];
        upk2(acc2[i][0], v[0], v[1]);
        upk2(acc2[i][1], v[2], v[3]);
#pragma unroll
        for (int j = 0; j < 4; j++)
            g_part[((size_t)g * 32 + co) * 12544 + nbase + tx * 4 + j] = v[j];
    }
}

// =====================================================================================
// K2b: reduce the 4 K-split partials + bias -> g_off (deterministic order)
// =====================================================================================
__global__ __launch_bounds__(256) void offreduce_kernel(const float* __restrict__ b_)
{
    int i = blockIdx.x * 256 + threadIdx.x;
    if (i < 32 * 12544) {
        int co = i / 12544, n = i % 12544;
        float s = ((g_part[(size_t)co * 12544 + n]
                  + g_part[((size_t)32 + co) * 12544 + n])
                  + g_part[((size_t)64 + co) * 12544 + n])
                  + g_part[((size_t)96 + co) * 12544 + n] + b_[co];
        int b = n / 196, p = n % 196, oh = p / 14, ow = p % 14;
        g_off[(((size_t)b * 32 + co) * 14 + oh) * 14 + ow] = s;
    }
}

// =====================================================================================
// K3a: bilinear gather -> split bf16 B (k = kk*96+c). 384 threads = (kk, c4) grid;
// each thread: 4 channels x 4 taps as float4 loads (coalesced per kk-group).
// =====================================================================================
__global__ __launch_bounds__(384) void gather_kernel()
{
    __shared__ float s_wy[16], s_wx[16];
    __shared__ int   s_y0[16], s_x0[16];

    int bp = blockIdx.x;
    int b = bp / 196, p = bp % 196;
    int oh = p / 14, ow = p % 14;
    int tid = threadIdx.x;

    if (tid < 16) {
        int kk = tid;
        float o0 = g_off[(((size_t)b * 32 + 2 * kk + 0) * 14 + oh) * 14 + ow];
        float o1 = g_off[(((size_t)b * 32 + 2 * kk + 1) * 14 + oh) * 14 + ow];
        float py = (float)(oh * 4 + (kk >> 2)) + o0;
        float px = (float)(ow * 4 + (kk & 3)) + o1;
        float y0f = floorf(py), x0f = floorf(px);
        s_y0[kk] = (int)y0f; s_x0[kk] = (int)x0f;
        s_wy[kk] = py - y0f; s_wx[kk] = px - x0f;
    }
    __syncthreads();

    int kk = tid / 24, c4 = tid % 24;
    int y0 = s_y0[kk], x0 = s_x0[kk];
    float wy = s_wy[kk], wx = s_wx[kk];
    int y1 = y0 + 1, x1 = x0 + 1;
    bool vy0 = (y0 >= 0) & (y0 < 56), vy1 = (y1 >= 0) & (y1 < 56);
    bool vx0 = (x0 >= 0) & (x0 < 56), vx1 = (x1 >= 0) & (x1 < 56);
    int yc0 = min(max(y0, 0), 55), yc1 = min(max(y1, 0), 55);
    int xc0 = min(max(x0, 0), 55), xc1 = min(max(x1, 0), 55);

    const float* hb = g_h + (size_t)b * 3136 * 96 + c4 * 4;
    const float4 z = make_float4(0.f, 0.f, 0.f, 0.f);
    float4 v00 = (vy0 & vx0) ? *(const float4*)(hb + ((size_t)yc0 * 56 + xc0) * 96) : z;
    float4 v01 = (vy0 & vx1) ? *(const float4*)(hb + ((size_t)yc0 * 56 + xc1) * 96) : z;
    float4 v10 = (vy1 & vx0) ? *(const float4*)(hb + ((size_t)yc1 * 56 + xc0) * 96) : z;
    float4 v11 = (vy1 & vx1) ? *(const float4*)(hb + ((size_t)yc1 * 56 + xc1) * 96) : z;

    float w00 = (1.f - wy) * (1.f - wx), w01 = (1.f - wy) * wx;
    float w10 = wy * (1.f - wx),         w11 = wy * wx;

    float r[4];
    r[0] = v00.x * w00 + v01.x * w01 + v10.x * w10 + v11.x * w11;
    r[1] = v00.y * w00 + v01.y * w01 + v10.y * w10 + v11.y * w11;
    r[2] = v00.z * w00 + v01.z * w01 + v10.z * w10 + v11.z * w11;
    r[3] = v00.w * w00 + v01.w * w01 + v10.w * w10 + v11.w * w11;

    size_t idx = (size_t)bp * 1536 + kk * 96 + c4 * 4;
    __nv_bfloat16 h0 = __float2bfloat16(r[0]);
    __nv_bfloat16 h1 = __float2bfloat16(r[1]);
    __nv_bfloat16 h2 = __float2bfloat16(r[2]);
    __nv_bfloat16 h3 = __float2bfloat16(r[3]);
    *(__nv_bfloat162*)(g_Bhi + idx)     = __halves2bfloat162(h0, h1);
    *(__nv_bfloat162*)(g_Bhi + idx + 2) = __halves2bfloat162(h2, h3);
    *(__nv_bfloat162*)(g_Blo + idx) = __halves2bfloat162(
        __float2bfloat16(r[0] - __bfloat162float(h0)),
        __float2bfloat16(r[1] - __bfloat162float(h1)));
    *(__nv_bfloat162*)(g_Blo + idx + 2) = __halves2bfloat162(
        __float2bfloat16(r[2] - __bfloat162float(h2)),
        __float2bfloat16(r[3] - __bfloat162float(h3)));
}

// =====================================================================================
// K3w: split + permute dcn_w -> g_Ahi/g_Alo with k = kk*96+c
// =====================================================================================
__global__ __launch_bounds__(256) void convw_kernel(const float* __restrict__ w)
{
    size_t i = (size_t)blockIdx.x * 256 + threadIdx.x;
    if (i < (size_t)768 * 1536) {
        int o = (int)(i / 1536), r = (int)(i % 1536);
        int kk = r / 96, c = r % 96;
        float v = w[(size_t)o * 1536 + c * 16 + kk];
        __nv_bfloat16 hi = __float2bfloat16(v);
        g_Ahi[i] = hi;
        g_Alo[i] = __float2bfloat16(v - __bfloat162float(hi));
    }
}

// =====================================================================================
// K3b: split-bf16 tensor-core GEMM via mma.sync (unchanged — proven)
// =====================================================================================
#define BK          64
#define NKB         24
#define STAGE       65536
#define S_AHI       0
#define S_ALO       16384
#define S_BHI       32768
#define S_BLO       49152
#define SMEM_TOTAL  (2 * STAGE)

__global__ __launch_bounds__(256, 1) void dcn_mma_kernel(
    const float* __restrict__ db,
    const float* __restrict__ bg, const float* __restrict__ bb,
    const float* __restrict__ bm, const float* __restrict__ bv,
    float* __restrict__ out)
{
    extern __shared__ char smem[];
    __shared__ float s_sc[128], s_sh[128];

    const uint32_t smem_u = smem_to_u32(smem);
    const int tid = threadIdx.x, lane = tid & 31, wid = tid >> 5;
    const int wm = wid >> 2, wn = wid & 3;
    const int obase = blockIdx.x * 128;
    const int nbase = blockIdx.y * 128;

    for (int i = tid; i < 128; i += 256) {
        int o = obase + i;
        float s = bg[o] * rsqrtf(bv[o] + EPSV);
        s_sc[i] = s;
        s_sh[i] = db[o] * s + bb[o] - bm[o] * s;
    }

    int lr[4], lkc[4];
    uint32_t lso[4];
#pragma unroll
    for (int it = 0; it < 4; it++) {
        int c = tid + it * 256;
        lr[it] = c >> 3; lkc[it] = c & 7;
        uint32_t so = (uint32_t)(lr[it] * 128 + lkc[it] * 16);
        lso[it] = so ^ ((so >> 3) & 0x70);
    }

    float acc[4][4][4];
#pragma unroll
    for (int i = 0; i < 4; i++)
#pragma unroll
        for (int j = 0; j < 4; j++)
#pragma unroll
            for (int q = 0; q < 4; q++) acc[i][j][q] = 0.f;

    {
        uint32_t sb = smem_u;
#pragma unroll
        for (int it = 0; it < 4; it++) {
            size_t ga = (size_t)(obase + lr[it]) * 1536 + lkc[it] * 8;
            size_t gb = (size_t)(nbase + lr[it]) * 1536 + lkc[it] * 8;
            cp16(sb + S_AHI + lso[it], g_Ahi + ga);
            cp16(sb + S_ALO + lso[it], g_Alo + ga);
            cp16(sb + S_BHI + lso[it], g_Bhi + gb);
            cp16(sb + S_BLO + lso[it], g_Blo + gb);
        }
        CP_COMMIT();
    }

    for (int kb = 0; kb < NKB; kb++) {
        CP_WAIT0();
        __syncthreads();

        if (kb + 1 < NKB) {
            uint32_t sb = smem_u + ((kb + 1) & 1) * STAGE;
            int k0 = (kb + 1) * BK;
#pragma unroll
            for (int it = 0; it < 4; it++) {
                size_t ga = (size_t)(obase + lr[it]) * 1536 + k0 + lkc[it] * 8;
                size_t gb = (size_t)(nbase + lr[it]) * 1536 + k0 + lkc[it] * 8;
                cp16(sb + S_AHI + lso[it], g_Ahi + ga);
                cp16(sb + S_ALO + lso[it], g_Alo + ga);
                cp16(sb + S_BHI + lso[it], g_Bhi + gb);
                cp16(sb + S_BLO + lso[it], g_Blo + gb);
            }
        }
        CP_COMMIT();

        const uint32_t cb = smem_u + (kb & 1) * STAGE;
#pragma unroll
        for (int k16 = 0; k16 < 4; k16++) {
            uint32_t a_hi[4][4], a_lo[4][4], b_hi[2][4], b_lo[2][4];
            {
                int chunk = k16 * 2 + (lane >> 4);
#pragma unroll
                for (int i = 0; i < 4; i++) {
                    int row = wm * 64 + i * 16 + (lane & 15);
                    uint32_t so = (uint32_t)(row * 128 + chunk * 16);
                    so ^= ((so >> 3) & 0x70);
                    ldsm4(a_hi[i], cb + S_AHI + so);
                    ldsm4(a_lo[i], cb + S_ALO + so);
                }
            }
            {
                int g = lane >> 3;
#pragma unroll
                for (int t = 0; t < 2; t++) {
                    int row = wn * 32 + (t * 2 + (g >> 1)) * 8 + (lane & 7);
                    int chunk = k16 * 2 + (g & 1);
                    uint32_t so = (uint32_t)(row * 128 + chunk * 16);
                    so ^= ((so >> 3) & 0x70);
                    ldsm4(b_hi[t], cb + S_BHI + so);
                    ldsm4(b_lo[t], cb + S_BLO + so);
                }
            }
#pragma unroll
            for (int i = 0; i < 4; i++)
#pragma unroll
                for (int j = 0; j < 4; j++) {
                    int t = j >> 1, pr = (j & 1) * 2;
                    mma16816(acc[i][j], a_hi[i], b_hi[t][pr], b_hi[t][pr + 1]);
                    mma16816(acc[i][j], a_hi[i], b_lo[t][pr], b_lo[t][pr + 1]);
                    mma16816(acc[i][j], a_lo[i], b_hi[t][pr], b_hi[t][pr + 1]);
                }
        }
        __syncthreads();
    }

    float* Csm = (float*)smem;
#pragma unroll
    for (int i = 0; i < 4; i++)
#pragma unroll
        for (int j = 0; j < 4; j++) {
            int nl = wn * 32 + j * 8 + 2 * (lane & 3);
            int ol = wm * 64 + i * 16 + (lane >> 2);
            Csm[(size_t)nl * 132 + ol]            = acc[i][j][0];
            Csm[(size_t)(nl + 1) * 132 + ol]      = acc[i][j][1];
            Csm[(size_t)nl * 132 + ol + 8]        = acc[i][j][2];
            Csm[(size_t)(nl + 1) * 132 + ol + 8]  = acc[i][j][3];
        }
    __syncthreads();

    for (int idx = tid; idx < 128 * 32; idx += 256) {
        int nl = idx >> 5, o4 = (idx & 31) * 4;
        float4 v = *(const float4*)&Csm[(size_t)nl * 132 + o4];
        v.x = lrelu(v.x * s_sc[o4 + 0] + s_sh[o4 + 0]);
        v.y = lrelu(v.y * s_sc[o4 + 1] + s_sh[o4 + 1]);
        v.z = lrelu(v.z * s_sc[o4 + 2] + s_sh[o4 + 2]);
        v.w = lrelu(v.w * s_sc[o4 + 3] + s_sh[o4 + 3]);
        *(float4*)&out[(size_t)(nbase + nl) * 768 + obase + o4] = v;
    }
}

// =====================================================================================
extern "C" void kernel_launch(void* const* d_in, const int* in_sizes, int n_in,
                              void* d_out, int out_size)
{
    const float* x      = (const float*)d_in[0];
    const float* stem_w = (const float*)d_in[1];
    const float* stem_b = (const float*)d_in[2];
    const float* bn1_g  = (const float*)d_in[3];
    const float* bn1_b  = (const float*)d_in[4];
    const float* bn1_m  = (const float*)d_in[5];
    const float* bn1_v  = (const float*)d_in[6];
    const float* off_w  = (const float*)d_in[7];
    const float* off_b  = (const float*)d_in[8];
    const float* dcn_w  = (const float*)d_in[9];
    const float* dcn_b  = (const float*)d_in[10];
    const float* bn2_g  = (const float*)d_in[11];
    const float* bn2_b  = (const float*)d_in[12];
    const float* bn2_m  = (const float*)d_in[13];
    const float* bn2_v  = (const float*)d_in[14];
    float* out = (float*)d_out;

    cudaFuncSetAttribute(dcn_mma_kernel, cudaFuncAttributeMaxDynamicSharedMemorySize, SMEM_TOTAL);
    cudaFuncSetAttribute(offconv_part_kernel, cudaFuncAttributeMaxDynamicSharedMemorySize, OC_SMEM);

    stem_kernel<<<64 * 49, 256>>>(x, stem_w, stem_b, bn1_g, bn1_b, bn1_m, bn1_v);
    offw_perm_kernel<<<(32 * 1536 + 255) / 256, 256>>>(off_w);
    convw_kernel<<<(768 * 1536 + 255) / 256, 256>>>(dcn_w);
    offconv_part_kernel<<<dim3(98, 4), 256, OC_SMEM>>>();
    offreduce_kernel<<<(32 * 12544 + 255) / 256, 256>>>(off_b);
    gather_kernel<<<64 * 196, 384>>>();
    dcn_mma_kernel<<<dim3(6, 98), 256, SMEM_TOTAL>>>(dcn_b, bn2_g, bn2_b, bn2_m, bn2_v, out);
}

// round 12
// speedup vs baseline: 2.9006x; 1.1625x over previous
#include <cuda_runtime.h>
#include <cuda_fp16.h>
#include <cstdint>

#define EPSV  1e-5f
#define SLOPE 0.01f

// ---------------- scratch (static device memory; no allocs allowed) ----------------
__device__ float g_h[(size_t)64 * 56 * 56 * 96];       // stem output, CHANNEL-LAST [b][y][x][c]
__device__ float g_off[(size_t)64 * 32 * 14 * 14];     // offsets
__device__ float g_offw[32 * 1536];                    // off_w permuted [kk][c][co]
__device__ float g_part[(size_t)8 * 32 * 12544];       // offconv K-split partials (8 groups)
__device__ __half g_Bf[(size_t)12544 * 1536];          // gathered samples, single fp16 (k=kk*96+c)
__device__ __half g_Ahi[(size_t)768 * 1536];           // dcn_w fp16 hi (k = kk*96+c)
__device__ __half g_Alo[(size_t)768 * 1536];           // dcn_w fp16 lo (residual)

__device__ __forceinline__ float lrelu(float x) { return x >= 0.f ? x : SLOPE * x; }

__device__ __forceinline__ uint32_t smem_to_u32(const void* p) {
    uint32_t a;
    asm("{ .reg .u64 t; cvta.to.shared.u64 t, %1; cvt.u32.u64 %0, t; }" : "=r"(a) : "l"(p));
    return a;
}
__device__ __forceinline__ void cp16(uint32_t dst, const void* src) {
    asm volatile("cp.async.cg.shared.global [%0], [%1], 16;" :: "r"(dst), "l"(src));
}
#define CP_COMMIT() asm volatile("cp.async.commit_group;" ::: "memory")
#define CP_WAIT1()  asm volatile("cp.async.wait_group 1;" ::: "memory")

__device__ __forceinline__ void ldsm4(uint32_t* r, uint32_t addr) {
    asm volatile("ldmatrix.sync.aligned.m8n8.x4.shared.b16 {%0,%1,%2,%3}, [%4];"
                 : "=r"(r[0]), "=r"(r[1]), "=r"(r[2]), "=r"(r[3]) : "r"(addr));
}
__device__ __forceinline__ void mma16816h(float* c, const uint32_t* a, uint32_t b0, uint32_t b1) {
    asm volatile(
        "mma.sync.aligned.m16n8k16.row.col.f32.f16.f16.f32 "
        "{%0,%1,%2,%3}, {%4,%5,%6,%7}, {%8,%9}, {%0,%1,%2,%3};"
        : "+f"(c[0]), "+f"(c[1]), "+f"(c[2]), "+f"(c[3])
        : "r"(a[0]), "r"(a[1]), "r"(a[2]), "r"(a[3]), "r"(b0), "r"(b1));
}

// packed f32x2 helpers
__device__ __forceinline__ unsigned long long pk2(float x, float y) {
    unsigned long long r;
    asm("mov.b64 %0,{%1,%2};" : "=l"(r) : "f"(x), "f"(y));
    return r;
}
__device__ __forceinline__ unsigned long long fma2(unsigned long long a,
                                                   unsigned long long b,
                                                   unsigned long long c) {
    unsigned long long d;
    asm("fma.rn.f32x2 %0,%1,%2,%3;" : "=l"(d) : "l"(a), "l"(b), "l"(c));
    return d;
}
__device__ __forceinline__ void upk2(unsigned long long v, float& lo, float& hi) {
    asm("mov.b64 {%0,%1},%2;" : "=f"(lo), "=f"(hi) : "l"(v));
}

// =====================================================================================
// K1: stem conv (4x4 stride4) + BN1 + leaky ReLU, f32x2 accumulation,
// channel-last output via smem transpose (coalesced store groups).
// =====================================================================================
__global__ __launch_bounds__(256) void stem_kernel(
    const float* __restrict__ x, const float* __restrict__ sw, const float* __restrict__ sb,
    const float* __restrict__ bg, const float* __restrict__ bb, const float* __restrict__ bm,
    const float* __restrict__ bv)
{
    __shared__ float wst[48][96];
    __shared__ float s_bb[96];
    __shared__ float s_sc[96];
    __shared__ float hout[64][100];   // padded: conflict-free STS.128

    int tid = threadIdx.x;
    for (int i = tid; i < 96; i += 256) {
        float sc = bg[i] * rsqrtf(bv[i] + EPSV);
        s_sc[i] = sc;
        s_bb[i] = sb[i] * sc + bb[i] - bm[i] * sc;
    }
    __syncthreads();
    for (int i = tid; i < 96 * 48; i += 256) {
        int co = i / 48, k = i % 48;
        wst[k][co] = sw[i] * s_sc[co];
    }
    __syncthreads();

    int b = blockIdx.x / 49;
    int sblk = (blockIdx.x % 49) * 64;
    int sl = tid & 63;
    int s = sblk + sl;
    int quarter = tid >> 6;
    int oh = s / 56, ow = s % 56;

    float patch[48];
    const float* xb = x + (size_t)b * 3 * 224 * 224;
#pragma unroll
    for (int ci = 0; ci < 3; ci++)
#pragma unroll
        for (int r = 0; r < 4; r++) {
            float4 p4 = *(const float4*)(xb + ((size_t)ci * 224 + oh * 4 + r) * 224 + ow * 4);
            patch[ci * 16 + r * 4 + 0] = p4.x;
            patch[ci * 16 + r * 4 + 1] = p4.y;
            patch[ci * 16 + r * 4 + 2] = p4.z;
            patch[ci * 16 + r * 4 + 3] = p4.w;
        }

#pragma unroll
    for (int gq = 0; gq < 6; gq++) {
        int co = quarter * 24 + gq * 4;
        unsigned long long a01 = pk2(s_bb[co], s_bb[co + 1]);
        unsigned long long a23 = pk2(s_bb[co + 2], s_bb[co + 3]);
#pragma unroll
        for (int k = 0; k < 48; k++) {
            float4 w4 = *(const float4*)&wst[k][co];
            unsigned long long pv2 = pk2(patch[k], patch[k]);
            a01 = fma2(pv2, pk2(w4.x, w4.y), a01);
            a23 = fma2(pv2, pk2(w4.z, w4.w), a23);
        }
        float t0, t1, t2, t3;
        upk2(a01, t0, t1); upk2(a23, t2, t3);
        float4 v;
        v.x = lrelu(t0); v.y = lrelu(t1); v.z = lrelu(t2); v.w = lrelu(t3);
        *(float4*)&hout[sl][co] = v;
    }
    __syncthreads();

    float* hb = g_h + ((size_t)b * 3136 + sblk) * 96;
    for (int e = tid; e < 64 * 24; e += 256) {
        int slo = e / 24, c4 = e % 24;
        *(float4*)(hb + (size_t)slo * 96 + c4 * 4) = *(const float4*)&hout[slo][c4 * 4];
    }
}

// =====================================================================================
// K1b: permute off_w -> g_offw[kk][c][co]
// =====================================================================================
__global__ __launch_bounds__(256) void offw_perm_kernel(const float* __restrict__ w)
{
    int i = blockIdx.x * 256 + threadIdx.x;
    if (i < 32 * 1536) {
        int kk = i / 3072, r = i % 3072, c = r / 32, co = r & 31;
        g_offw[i] = w[(size_t)co * 1536 + c * 16 + kk];
    }
}

// =====================================================================================
// K2a: offset conv partial GEMM, K split 8 ways (784 CTAs -> latency hidden).
// grid (98, 8): block = 128 positions x 2 kk taps -> g_part[g][co][n].
// =====================================================================================
#define OC_SMEM ((96 * 128 + 96 * 32) * 4)
__global__ __launch_bounds__(256) void offconv_part_kernel()
{
    extern __shared__ float sm[];
    float* Pt = sm;             // [96][128] k-major
    float* Wt = sm + 96 * 128;  // [96][32]  k-major

    int tid = threadIdx.x;
    int nbase = blockIdx.x * 128;
    int g = blockIdx.y;
    int tx = tid & 31, ty = tid >> 5;   // tx: 4-n group, ty: 4-co group

    unsigned long long acc2[4][2];
#pragma unroll
    for (int i = 0; i < 4; i++) { acc2[i][0] = 0ull; acc2[i][1] = 0ull; }

    for (int kb = g * 2; kb < g * 2 + 2; kb++) {
        int kh = kb >> 2, kw = kb & 3;
        for (int e = tid; e < 3072; e += 256)          // Wt[c][co] <- g_offw coalesced
            Wt[e] = g_offw[kb * 3072 + e];
        for (int e = tid; e < 3072; e += 256) {        // Pt[k][ni]
            int c4 = e >> 7, ni = e & 127;
            int n = nbase + ni, b = n / 196, p = n % 196;
            int oh = p / 14, ow = p % 14;
            float4 v = *(const float4*)(g_h +
                ((size_t)b * 3136 + (oh * 4 + kh) * 56 + ow * 4 + kw) * 96 + c4 * 4);
            int k0 = c4 * 4;
            Pt[(k0 + 0) * 128 + ni] = v.x;
            Pt[(k0 + 1) * 128 + ni] = v.y;
            Pt[(k0 + 2) * 128 + ni] = v.z;
            Pt[(k0 + 3) * 128 + ni] = v.w;
        }
        __syncthreads();

#pragma unroll 4
        for (int k = 0; k < 96; k++) {
            float4 wv = *(const float4*)&Wt[k * 32 + ty * 4];
            float4 pv = *(const float4*)&Pt[k * 128 + tx * 4];
            unsigned long long p01 = pk2(pv.x, pv.y), p23 = pk2(pv.z, pv.w);
            acc2[0][0] = fma2(pk2(wv.x, wv.x), p01, acc2[0][0]);
            acc2[0][1] = fma2(pk2(wv.x, wv.x), p23, acc2[0][1]);
            acc2[1][0] = fma2(pk2(wv.y, wv.y), p01, acc2[1][0]);
            acc2[1][1] = fma2(pk2(wv.y, wv.y), p23, acc2[1][1]);
            acc2[2][0] = fma2(pk2(wv.z, wv.z), p01, acc2[2][0]);
            acc2[2][1] = fma2(pk2(wv.z, wv.z), p23, acc2[2][1]);
            acc2[3][0] = fma2(pk2(wv.w, wv.w), p01, acc2[3][0]);
            acc2[3][1] = fma2(pk2(wv.w, wv.w), p23, acc2[3][1]);
        }
        __syncthreads();
    }

#pragma unroll
    for (int i = 0; i < 4; i++) {
        int co = ty * 4 + i;
        float v[4];
        upk2(acc2[i][0], v[0], v[1]);
        upk2(acc2[i][1], v[2], v[3]);
#pragma unroll
        for (int j = 0; j < 4; j++)
            g_part[((size_t)g * 32 + co) * 12544 + nbase + tx * 4 + j] = v[j];
    }
}

// =====================================================================================
// K2b: reduce the 8 K-split partials + bias -> g_off (deterministic order)
// =====================================================================================
__global__ __launch_bounds__(256) void offreduce_kernel(const float* __restrict__ b_)
{
    int i = blockIdx.x * 256 + threadIdx.x;
    if (i < 32 * 12544) {
        int co = i / 12544, n = i % 12544;
        float s = b_[co];
#pragma unroll
        for (int g = 0; g < 8; g++)
            s += g_part[((size_t)g * 32 + co) * 12544 + n];
        int b = n / 196, p = n % 196, oh = p / 14, ow = p % 14;
        g_off[(((size_t)b * 32 + co) * 14 + oh) * 14 + ow] = s;
    }
}

// =====================================================================================
// K3a: bilinear gather -> single fp16 B (k = kk*96+c). 384 threads = (kk, c4) grid.
// =====================================================================================
__global__ __launch_bounds__(384) void gather_kernel()
{
    __shared__ float s_wy[16], s_wx[16];
    __shared__ int   s_y0[16], s_x0[16];

    int bp = blockIdx.x;
    int b = bp / 196, p = bp % 196;
    int oh = p / 14, ow = p % 14;
    int tid = threadIdx.x;

    if (tid < 16) {
        int kk = tid;
        float o0 = g_off[(((size_t)b * 32 + 2 * kk + 0) * 14 + oh) * 14 + ow];
        float o1 = g_off[(((size_t)b * 32 + 2 * kk + 1) * 14 + oh) * 14 + ow];
        float py = (float)(oh * 4 + (kk >> 2)) + o0;
        float px = (float)(ow * 4 + (kk & 3)) + o1;
        float y0f = floorf(py), x0f = floorf(px);
        s_y0[kk] = (int)y0f; s_x0[kk] = (int)x0f;
        s_wy[kk] = py - y0f; s_wx[kk] = px - x0f;
    }
    __syncthreads();

    int kk = tid / 24, c4 = tid % 24;
    int y0 = s_y0[kk], x0 = s_x0[kk];
    float wy = s_wy[kk], wx = s_wx[kk];
    int y1 = y0 + 1, x1 = x0 + 1;
    bool vy0 = (y0 >= 0) & (y0 < 56), vy1 = (y1 >= 0) & (y1 < 56);
    bool vx0 = (x0 >= 0) & (x0 < 56), vx1 = (x1 >= 0) & (x1 < 56);
    int yc0 = min(max(y0, 0), 55), yc1 = min(max(y1, 0), 55);
    int xc0 = min(max(x0, 0), 55), xc1 = min(max(x1, 0), 55);

    const float* hb = g_h + (size_t)b * 3136 * 96 + c4 * 4;
    const float4 z = make_float4(0.f, 0.f, 0.f, 0.f);
    float4 v00 = (vy0 & vx0) ? *(const float4*)(hb + ((size_t)yc0 * 56 + xc0) * 96) : z;
    float4 v01 = (vy0 & vx1) ? *(const float4*)(hb + ((size_t)yc0 * 56 + xc1) * 96) : z;
    float4 v10 = (vy1 & vx0) ? *(const float4*)(hb + ((size_t)yc1 * 56 + xc0) * 96) : z;
    float4 v11 = (vy1 & vx1) ? *(const float4*)(hb + ((size_t)yc1 * 56 + xc1) * 96) : z;

    float w00 = (1.f - wy) * (1.f - wx), w01 = (1.f - wy) * wx;
    float w10 = wy * (1.f - wx),         w11 = wy * wx;

    float r0 = v00.x * w00 + v01.x * w01 + v10.x * w10 + v11.x * w11;
    float r1 = v00.y * w00 + v01.y * w01 + v10.y * w10 + v11.y * w11;
    float r2 = v00.z * w00 + v01.z * w01 + v10.z * w10 + v11.z * w11;
    float r3 = v00.w * w00 + v01.w * w01 + v10.w * w10 + v11.w * w11;

    size_t idx = (size_t)bp * 1536 + kk * 96 + c4 * 4;
    *(__half2*)(g_Bf + idx)     = __floats2half2_rn(r0, r1);
    *(__half2*)(g_Bf + idx + 2) = __floats2half2_rn(r2, r3);
}

// =====================================================================================
// K3w: split + permute dcn_w -> fp16 g_Ahi/g_Alo with k = kk*96+c
// =====================================================================================
__global__ __launch_bounds__(256) void convw_kernel(const float* __restrict__ w)
{
    size_t i = (size_t)blockIdx.x * 256 + threadIdx.x;
    if (i < (size_t)768 * 1536) {
        int o = (int)(i / 1536), r = (int)(i % 1536);
        int kk = r / 96, c = r % 96;
        float v = w[(size_t)o * 1536 + c * 16 + kk];
        __half hi = __float2half_rn(v);
        g_Ahi[i] = hi;
        g_Alo[i] = __float2half_rn(v - __half2float(hi));
    }
}

// =====================================================================================
// K3b: 2-product fp16 tensor GEMM via mma.sync. C = (Ahi + Alo) · B.
// 128x128 CTA tile, BK=64, 3-stage cp.async ring (48KB/stage), 8 warps m64n32.
// Epilogue: BN2 + bias + lrelu, transpose via smem, coalesced float4 stores.
// =====================================================================================
#define BK          64
#define NKB         24
#define DSTAGE      49152
#define S_AHI       0
#define S_ALO       16384
#define S_BF        32768
#define SMEM_TOTAL  (3 * DSTAGE)

__global__ __launch_bounds__(256, 1) void dcn_mma_kernel(
    const float* __restrict__ db,
    const float* __restrict__ bg, const float* __restrict__ bb,
    const float* __restrict__ bm, const float* __restrict__ bv,
    float* __restrict__ out)
{
    extern __shared__ char smem[];
    __shared__ float s_sc[128], s_sh[128];

    const uint32_t smem_u = smem_to_u32(smem);
    const int tid = threadIdx.x, lane = tid & 31, wid = tid >> 5;
    const int wm = wid >> 2, wn = wid & 3;
    const int obase = blockIdx.x * 128;   // x fastest: 6 M-tiles of one N-column co-resident (B L2 reuse)
    const int nbase = blockIdx.y * 128;

    for (int i = tid; i < 128; i += 256) {
        int o = obase + i;
        float s = bg[o] * rsqrtf(bv[o] + EPSV);
        s_sc[i] = s;
        s_sh[i] = db[o] * s + bb[o] - bm[o] * s;
    }

    int lr[4], lkc[4];
    uint32_t lso[4];
#pragma unroll
    for (int it = 0; it < 4; it++) {
        int c = tid + it * 256;
        lr[it] = c >> 3; lkc[it] = c & 7;
        uint32_t so = (uint32_t)(lr[it] * 128 + lkc[it] * 16);
        lso[it] = so ^ ((so >> 3) & 0x70);
    }

    float acc[4][4][4];
#pragma unroll
    for (int i = 0; i < 4; i++)
#pragma unroll
        for (int j = 0; j < 4; j++)
#pragma unroll
            for (int q = 0; q < 4; q++) acc[i][j][q] = 0.f;

#define ISSUE_STAGE(kb_) do {                                              \
        uint32_t sb = smem_u + ((kb_) % 3) * DSTAGE;                       \
        int k0 = (kb_) * BK;                                               \
        _Pragma("unroll")                                                  \
        for (int it = 0; it < 4; it++) {                                   \
            size_t ga = (size_t)(obase + lr[it]) * 1536 + k0 + lkc[it] * 8;\
            size_t gb = (size_t)(nbase + lr[it]) * 1536 + k0 + lkc[it] * 8;\
            cp16(sb + S_AHI + lso[it], g_Ahi + ga);                        \
            cp16(sb + S_ALO + lso[it], g_Alo + ga);                        \
            cp16(sb + S_BF  + lso[it], g_Bf  + gb);                        \
        }                                                                  \
    } while (0)

    ISSUE_STAGE(0); CP_COMMIT();
    ISSUE_STAGE(1); CP_COMMIT();

    for (int kb = 0; kb < NKB; kb++) {
        CP_WAIT1();
        __syncthreads();

        if (kb + 2 < NKB) ISSUE_STAGE(kb + 2);
        CP_COMMIT();

        const uint32_t cb = smem_u + (kb % 3) * DSTAGE;
#pragma unroll
        for (int k16 = 0; k16 < 4; k16++) {
            uint32_t a_hi[4][4], a_lo[4][4], b_f[2][4];
            {
                int chunk = k16 * 2 + (lane >> 4);
#pragma unroll
                for (int i = 0; i < 4; i++) {
                    int row = wm * 64 + i * 16 + (lane & 15);
                    uint32_t so = (uint32_t)(row * 128 + chunk * 16);
                    so ^= ((so >> 3) & 0x70);
                    ldsm4(a_hi[i], cb + S_AHI + so);
                    ldsm4(a_lo[i], cb + S_ALO + so);
                }
            }
            {
                int g = lane >> 3;
#pragma unroll
                for (int t = 0; t < 2; t++) {
                    int row = wn * 32 + (t * 2 + (g >> 1)) * 8 + (lane & 7);
                    int chunk = k16 * 2 + (g & 1);
                    uint32_t so = (uint32_t)(row * 128 + chunk * 16);
                    so ^= ((so >> 3) & 0x70);
                    ldsm4(b_f[t], cb + S_BF + so);
                }
            }
#pragma unroll
            for (int i = 0; i < 4; i++)
#pragma unroll
                for (int j = 0; j < 4; j++) {
                    int t = j >> 1, pr = (j & 1) * 2;
                    mma16816h(acc[i][j], a_hi[i], b_f[t][pr], b_f[t][pr + 1]);
                    mma16816h(acc[i][j], a_lo[i], b_f[t][pr], b_f[t][pr + 1]);
                }
        }
        __syncthreads();
    }

    // ---- epilogue: C -> smem (n-major, o contiguous, pad 132) -> BN+lrelu -> out ----
    float* Csm = (float*)smem;
#pragma unroll
    for (int i = 0; i < 4; i++)
#pragma unroll
        for (int j = 0; j < 4; j++) {
            int nl = wn * 32 + j * 8 + 2 * (lane & 3);
            int ol = wm * 64 + i * 16 + (lane >> 2);
            Csm[(size_t)nl * 132 + ol]            = acc[i][j][0];
            Csm[(size_t)(nl + 1) * 132 + ol]      = acc[i][j][1];
            Csm[(size_t)nl * 132 + ol + 8]        = acc[i][j][2];
            Csm[(size_t)(nl + 1) * 132 + ol + 8]  = acc[i][j][3];
        }
    __syncthreads();

    for (int idx = tid; idx < 128 * 32; idx += 256) {
        int nl = idx >> 5, o4 = (idx & 31) * 4;
        float4 v = *(const float4*)&Csm[(size_t)nl * 132 + o4];
        v.x = lrelu(v.x * s_sc[o4 + 0] + s_sh[o4 + 0]);
        v.y = lrelu(v.y * s_sc[o4 + 1] + s_sh[o4 + 1]);
        v.z = lrelu(v.z * s_sc[o4 + 2] + s_sh[o4 + 2]);
        v.w = lrelu(v.w * s_sc[o4 + 3] + s_sh[o4 + 3]);
        *(float4*)&out[(size_t)(nbase + nl) * 768 + obase + o4] = v;
    }
}

// =====================================================================================
extern "C" void kernel_launch(void* const* d_in, const int* in_sizes, int n_in,
                              void* d_out, int out_size)
{
    const float* x      = (const float*)d_in[0];
    const float* stem_w = (const float*)d_in[1];
    const float* stem_b = (const float*)d_in[2];
    const float* bn1_g  = (const float*)d_in[3];
    const float* bn1_b  = (const float*)d_in[4];
    const float* bn1_m  = (const float*)d_in[5];
    const float* bn1_v  = (const float*)d_in[6];
    const float* off_w  = (const float*)d_in[7];
    const float* off_b  = (const float*)d_in[8];
    const float* dcn_w  = (const float*)d_in[9];
    const float* dcn_b  = (const float*)d_in[10];
    const float* bn2_g  = (const float*)d_in[11];
    const float* bn2_b  = (const float*)d_in[12];
    const float* bn2_m  = (const float*)d_in[13];
    const float* bn2_v  = (const float*)d_in[14];
    float* out = (float*)d_out;

    cudaFuncSetAttribute(dcn_mma_kernel, cudaFuncAttributeMaxDynamicSharedMemorySize, SMEM_TOTAL);
    cudaFuncSetAttribute(offconv_part_kernel, cudaFuncAttributeMaxDynamicSharedMemorySize, OC_SMEM);

    stem_kernel<<<64 * 49, 256>>>(x, stem_w, stem_b, bn1_g, bn1_b, bn1_m, bn1_v);
    offw_perm_kernel<<<(32 * 1536 + 255) / 256, 256>>>(off_w);
    convw_kernel<<<(768 * 1536 + 255) / 256, 256>>>(dcn_w);
    offconv_part_kernel<<<dim3(98, 8), 256, OC_SMEM>>>();
    offreduce_kernel<<<(32 * 12544 + 255) / 256, 256>>>(off_b);
    gather_kernel<<<64 * 196, 384>>>();
    dcn_mma_kernel<<<dim3(6, 98), 256, SMEM_TOTAL>>>(dcn_b, bn2_g, bn2_b, bn2_m, bn2_v, out);
}

// round 13
// speedup vs baseline: 3.2741x; 1.1288x over previous
#include <cuda_runtime.h>
#include <cuda_fp16.h>
#include <cstdint>

#define EPSV  1e-5f
#define SLOPE 0.01f

// ---------------- scratch (static device memory; no allocs allowed) ----------------
__device__ float g_h[(size_t)64 * 56 * 56 * 96];       // stem output, CHANNEL-LAST [b][y][x][c]
__device__ float g_off[(size_t)64 * 32 * 14 * 14];     // offsets
__device__ float g_offw[32 * 1536];                    // off_w permuted [kk][c][co]
__device__ float g_part[(size_t)8 * 32 * 12544];       // offconv K-split partials (8 groups)
__device__ __half g_Bf[(size_t)12544 * 1536];          // gathered samples, fp16 (k=kk*96+c)
__device__ __half g_Af[(size_t)768 * 1536];            // dcn_w fp16 (k = kk*96+c)

__device__ __forceinline__ float lrelu(float x) { return x >= 0.f ? x : SLOPE * x; }

__device__ __forceinline__ uint32_t smem_to_u32(const void* p) {
    uint32_t a;
    asm("{ .reg .u64 t; cvta.to.shared.u64 t, %1; cvt.u32.u64 %0, t; }" : "=r"(a) : "l"(p));
    return a;
}
__device__ __forceinline__ void cp16(uint32_t dst, const void* src) {
    asm volatile("cp.async.cg.shared.global [%0], [%1], 16;" :: "r"(dst), "l"(src));
}
#define CP_COMMIT() asm volatile("cp.async.commit_group;" ::: "memory")
#define CP_WAIT1()  asm volatile("cp.async.wait_group 1;" ::: "memory")

__device__ __forceinline__ void ldsm4(uint32_t* r, uint32_t addr) {
    asm volatile("ldmatrix.sync.aligned.m8n8.x4.shared.b16 {%0,%1,%2,%3}, [%4];"
                 : "=r"(r[0]), "=r"(r[1]), "=r"(r[2]), "=r"(r[3]) : "r"(addr));
}
__device__ __forceinline__ void mma16816h(float* c, const uint32_t* a, uint32_t b0, uint32_t b1) {
    asm volatile(
        "mma.sync.aligned.m16n8k16.row.col.f32.f16.f16.f32 "
        "{%0,%1,%2,%3}, {%4,%5,%6,%7}, {%8,%9}, {%0,%1,%2,%3};"
        : "+f"(c[0]), "+f"(c[1]), "+f"(c[2]), "+f"(c[3])
        : "r"(a[0]), "r"(a[1]), "r"(a[2]), "r"(a[3]), "r"(b0), "r"(b1));
}

// packed f32x2 helpers
__device__ __forceinline__ unsigned long long pk2(float x, float y) {
    unsigned long long r;
    asm("mov.b64 %0,{%1,%2};" : "=l"(r) : "f"(x), "f"(y));
    return r;
}
__device__ __forceinline__ unsigned long long fma2(unsigned long long a,
                                                   unsigned long long b,
                                                   unsigned long long c) {
    unsigned long long d;
    asm("fma.rn.f32x2 %0,%1,%2,%3;" : "=l"(d) : "l"(a), "l"(b), "l"(c));
    return d;
}
__device__ __forceinline__ void upk2(unsigned long long v, float& lo, float& hi) {
    asm("mov.b64 {%0,%1},%2;" : "=f"(lo), "=f"(hi) : "l"(v));
}

// =====================================================================================
// K1: stem conv (4x4 stride4) + BN1 + leaky ReLU, f32x2 accumulation,
// channel-last output via smem transpose (coalesced store groups).
// =====================================================================================
__global__ __launch_bounds__(256) void stem_kernel(
    const float* __restrict__ x, const float* __restrict__ sw, const float* __restrict__ sb,
    const float* __restrict__ bg, const float* __restrict__ bb, const float* __restrict__ bm,
    const float* __restrict__ bv)
{
    __shared__ float wst[48][96];
    __shared__ float s_bb[96];
    __shared__ float s_sc[96];
    __shared__ float hout[64][100];   // padded: conflict-free STS.128

    int tid = threadIdx.x;
    for (int i = tid; i < 96; i += 256) {
        float sc = bg[i] * rsqrtf(bv[i] + EPSV);
        s_sc[i] = sc;
        s_bb[i] = sb[i] * sc + bb[i] - bm[i] * sc;
    }
    __syncthreads();
    for (int i = tid; i < 96 * 48; i += 256) {
        int co = i / 48, k = i % 48;
        wst[k][co] = sw[i] * s_sc[co];
    }
    __syncthreads();

    int b = blockIdx.x / 49;
    int sblk = (blockIdx.x % 49) * 64;
    int sl = tid & 63;
    int s = sblk + sl;
    int quarter = tid >> 6;
    int oh = s / 56, ow = s % 56;

    float patch[48];
    const float* xb = x + (size_t)b * 3 * 224 * 224;
#pragma unroll
    for (int ci = 0; ci < 3; ci++)
#pragma unroll
        for (int r = 0; r < 4; r++) {
            float4 p4 = *(const float4*)(xb + ((size_t)ci * 224 + oh * 4 + r) * 224 + ow * 4);
            patch[ci * 16 + r * 4 + 0] = p4.x;
            patch[ci * 16 + r * 4 + 1] = p4.y;
            patch[ci * 16 + r * 4 + 2] = p4.z;
            patch[ci * 16 + r * 4 + 3] = p4.w;
        }

#pragma unroll
    for (int gq = 0; gq < 6; gq++) {
        int co = quarter * 24 + gq * 4;
        unsigned long long a01 = pk2(s_bb[co], s_bb[co + 1]);
        unsigned long long a23 = pk2(s_bb[co + 2], s_bb[co + 3]);
#pragma unroll
        for (int k = 0; k < 48; k++) {
            float4 w4 = *(const float4*)&wst[k][co];
            unsigned long long pv2 = pk2(patch[k], patch[k]);
            a01 = fma2(pv2, pk2(w4.x, w4.y), a01);
            a23 = fma2(pv2, pk2(w4.z, w4.w), a23);
        }
        float t0, t1, t2, t3;
        upk2(a01, t0, t1); upk2(a23, t2, t3);
        float4 v;
        v.x = lrelu(t0); v.y = lrelu(t1); v.z = lrelu(t2); v.w = lrelu(t3);
        *(float4*)&hout[sl][co] = v;
    }
    __syncthreads();

    float* hb = g_h + ((size_t)b * 3136 + sblk) * 96;
    for (int e = tid; e < 64 * 24; e += 256) {
        int slo = e / 24, c4 = e % 24;
        *(float4*)(hb + (size_t)slo * 96 + c4 * 4) = *(const float4*)&hout[slo][c4 * 4];
    }
}

// =====================================================================================
// K1b: permute off_w -> g_offw[kk][c][co]
// =====================================================================================
__global__ __launch_bounds__(256) void offw_perm_kernel(const float* __restrict__ w)
{
    int i = blockIdx.x * 256 + threadIdx.x;
    if (i < 32 * 1536) {
        int kk = i / 3072, r = i % 3072, c = r / 32, co = r & 31;
        g_offw[i] = w[(size_t)co * 1536 + c * 16 + kk];
    }
}

// =====================================================================================
// K2a: offset conv partial GEMM, K split 8 ways, 512 threads (48 warps/SM resident).
// grid (98, 8): block = 128 positions x 2 kk taps -> g_part[g][co][n].
// =====================================================================================
#define OC_SMEM ((96 * 128 + 96 * 32) * 4)
__global__ __launch_bounds__(512) void offconv_part_kernel()
{
    extern __shared__ float sm[];
    float* Pt = sm;             // [96][128] k-major
    float* Wt = sm + 96 * 128;  // [96][32]  k-major

    int tid = threadIdx.x;
    int nbase = blockIdx.x * 128;
    int g = blockIdx.y;
    int tx = tid & 31, ty = tid >> 5;   // tx: 4-n group, ty (0..15): 2-co group

    unsigned long long acc2[2][2];
    acc2[0][0] = 0ull; acc2[0][1] = 0ull; acc2[1][0] = 0ull; acc2[1][1] = 0ull;

    for (int kb = g * 2; kb < g * 2 + 2; kb++) {
        int kh = kb >> 2, kw = kb & 3;
        for (int e = tid; e < 3072; e += 512)          // Wt[c][co] <- g_offw coalesced
            Wt[e] = g_offw[kb * 3072 + e];
        for (int e = tid; e < 3072; e += 512) {        // Pt[k][ni]
            int c4 = e >> 7, ni = e & 127;
            int n = nbase + ni, b = n / 196, p = n % 196;
            int oh = p / 14, ow = p % 14;
            float4 v = *(const float4*)(g_h +
                ((size_t)b * 3136 + (oh * 4 + kh) * 56 + ow * 4 + kw) * 96 + c4 * 4);
            int k0 = c4 * 4;
            Pt[(k0 + 0) * 128 + ni] = v.x;
            Pt[(k0 + 1) * 128 + ni] = v.y;
            Pt[(k0 + 2) * 128 + ni] = v.z;
            Pt[(k0 + 3) * 128 + ni] = v.w;
        }
        __syncthreads();

#pragma unroll 4
        for (int k = 0; k < 96; k++) {
            float2 wv = *(const float2*)&Wt[k * 32 + ty * 2];
            float4 pv = *(const float4*)&Pt[k * 128 + tx * 4];
            unsigned long long p01 = pk2(pv.x, pv.y), p23 = pk2(pv.z, pv.w);
            acc2[0][0] = fma2(pk2(wv.x, wv.x), p01, acc2[0][0]);
            acc2[0][1] = fma2(pk2(wv.x, wv.x), p23, acc2[0][1]);
            acc2[1][0] = fma2(pk2(wv.y, wv.y), p01, acc2[1][0]);
            acc2[1][1] = fma2(pk2(wv.y, wv.y), p23, acc2[1][1]);
        }
        __syncthreads();
    }

#pragma unroll
    for (int i = 0; i < 2; i++) {
        int co = ty * 2 + i;
        float v[4];
        upk2(acc2[i][0], v[0], v[1]);
        upk2(acc2[i][1], v[2], v[3]);
#pragma unroll
        for (int j = 0; j < 4; j++)
            g_part[((size_t)g * 32 + co) * 12544 + nbase + tx * 4 + j] = v[j];
    }
}

// =====================================================================================
// K2b: reduce the 8 K-split partials + bias -> g_off (deterministic order)
// =====================================================================================
__global__ __launch_bounds__(256) void offreduce_kernel(const float* __restrict__ b_)
{
    int i = blockIdx.x * 256 + threadIdx.x;
    if (i < 32 * 12544) {
        int co = i / 12544, n = i % 12544;
        float s = b_[co];
#pragma unroll
        for (int g = 0; g < 8; g++)
            s += g_part[((size_t)g * 32 + co) * 12544 + n];
        int b = n / 196, p = n % 196, oh = p / 14, ow = p % 14;
        g_off[(((size_t)b * 32 + co) * 14 + oh) * 14 + ow] = s;
    }
}

// =====================================================================================
// K3a: bilinear gather -> fp16 B (k = kk*96+c). 384 threads = (kk, c4) grid.
// =====================================================================================
__global__ __launch_bounds__(384) void gather_kernel()
{
    __shared__ float s_wy[16], s_wx[16];
    __shared__ int   s_y0[16], s_x0[16];

    int bp = blockIdx.x;
    int b = bp / 196, p = bp % 196;
    int oh = p / 14, ow = p % 14;
    int tid = threadIdx.x;

    if (tid < 16) {
        int kk = tid;
        float o0 = g_off[(((size_t)b * 32 + 2 * kk + 0) * 14 + oh) * 14 + ow];
        float o1 = g_off[(((size_t)b * 32 + 2 * kk + 1) * 14 + oh) * 14 + ow];
        float py = (float)(oh * 4 + (kk >> 2)) + o0;
        float px = (float)(ow * 4 + (kk & 3)) + o1;
        float y0f = floorf(py), x0f = floorf(px);
        s_y0[kk] = (int)y0f; s_x0[kk] = (int)x0f;
        s_wy[kk] = py - y0f; s_wx[kk] = px - x0f;
    }
    __syncthreads();

    int kk = tid / 24, c4 = tid % 24;
    int y0 = s_y0[kk], x0 = s_x0[kk];
    float wy = s_wy[kk], wx = s_wx[kk];
    int y1 = y0 + 1, x1 = x0 + 1;
    bool vy0 = (y0 >= 0) & (y0 < 56), vy1 = (y1 >= 0) & (y1 < 56);
    bool vx0 = (x0 >= 0) & (x0 < 56), vx1 = (x1 >= 0) & (x1 < 56);
    int yc0 = min(max(y0, 0), 55), yc1 = min(max(y1, 0), 55);
    int xc0 = min(max(x0, 0), 55), xc1 = min(max(x1, 0), 55);

    const float* hb = g_h + (size_t)b * 3136 * 96 + c4 * 4;
    const float4 z = make_float4(0.f, 0.f, 0.f, 0.f);
    float4 v00 = (vy0 & vx0) ? *(const float4*)(hb + ((size_t)yc0 * 56 + xc0) * 96) : z;
    float4 v01 = (vy0 & vx1) ? *(const float4*)(hb + ((size_t)yc0 * 56 + xc1) * 96) : z;
    float4 v10 = (vy1 & vx0) ? *(const float4*)(hb + ((size_t)yc1 * 56 + xc0) * 96) : z;
    float4 v11 = (vy1 & vx1) ? *(const float4*)(hb + ((size_t)yc1 * 56 + xc1) * 96) : z;

    float w00 = (1.f - wy) * (1.f - wx), w01 = (1.f - wy) * wx;
    float w10 = wy * (1.f - wx),         w11 = wy * wx;

    float r0 = v00.x * w00 + v01.x * w01 + v10.x * w10 + v11.x * w11;
    float r1 = v00.y * w00 + v01.y * w01 + v10.y * w10 + v11.y * w11;
    float r2 = v00.z * w00 + v01.z * w01 + v10.z * w10 + v11.z * w11;
    float r3 = v00.w * w00 + v01.w * w01 + v10.w * w10 + v11.w * w11;

    size_t idx = (size_t)bp * 1536 + kk * 96 + c4 * 4;
    *(__half2*)(g_Bf + idx)     = __floats2half2_rn(r0, r1);
    *(__half2*)(g_Bf + idx + 2) = __floats2half2_rn(r2, r3);
}

// =====================================================================================
// K3w: permute dcn_w -> fp16 g_Af with k = kk*96+c
// =====================================================================================
__global__ __launch_bounds__(256) void convw_kernel(const float* __restrict__ w)
{
    size_t i = (size_t)blockIdx.x * 256 + threadIdx.x;
    if (i < (size_t)768 * 1536) {
        int o = (int)(i / 1536), r = (int)(i % 1536);
        int kk = r / 96, c = r % 96;
        g_Af[i] = __float2half_rn(w[(size_t)o * 1536 + c * 16 + kk]);
    }
}

// =====================================================================================
// K3b: single-product fp16 tensor GEMM via mma.sync. C = A · B, fp32 accum.
// 128x128 CTA tile, BK=64, 3-stage cp.async ring (32KB/stage), 8 warps m64n32.
// Epilogue: BN2 + bias + lrelu, transpose via smem, coalesced float4 stores.
// =====================================================================================
#define BK          64
#define NKB         24
#define DSTAGE      32768
#define S_AF        0
#define S_BF        16384
#define SMEM_TOTAL  (3 * DSTAGE)

__global__ __launch_bounds__(256, 1) void dcn_mma_kernel(
    const float* __restrict__ db,
    const float* __restrict__ bg, const float* __restrict__ bb,
    const float* __restrict__ bm, const float* __restrict__ bv,
    float* __restrict__ out)
{
    extern __shared__ char smem[];
    __shared__ float s_sc[128], s_sh[128];

    const uint32_t smem_u = smem_to_u32(smem);
    const int tid = threadIdx.x, lane = tid & 31, wid = tid >> 5;
    const int wm = wid >> 2, wn = wid & 3;
    const int obase = blockIdx.x * 128;   // x fastest: 6 M-tiles of one N-column co-resident (B L2 reuse)
    const int nbase = blockIdx.y * 128;

    for (int i = tid; i < 128; i += 256) {
        int o = obase + i;
        float s = bg[o] * rsqrtf(bv[o] + EPSV);
        s_sc[i] = s;
        s_sh[i] = db[o] * s + bb[o] - bm[o] * s;
    }

    int lr[4], lkc[4];
    uint32_t lso[4];
#pragma unroll
    for (int it = 0; it < 4; it++) {
        int c = tid + it * 256;
        lr[it] = c >> 3; lkc[it] = c & 7;
        uint32_t so = (uint32_t)(lr[it] * 128 + lkc[it] * 16);
        lso[it] = so ^ ((so >> 3) & 0x70);
    }

    float acc[4][4][4];
#pragma unroll
    for (int i = 0; i < 4; i++)
#pragma unroll
        for (int j = 0; j < 4; j++)
#pragma unroll
            for (int q = 0; q < 4; q++) acc[i][j][q] = 0.f;

#define ISSUE_STAGE(kb_) do {                                              \
        uint32_t sb = smem_u + ((kb_) % 3) * DSTAGE;                       \
        int k0 = (kb_) * BK;                                               \
        _Pragma("unroll")                                                  \
        for (int it = 0; it < 4; it++) {                                   \
            size_t ga = (size_t)(obase + lr[it]) * 1536 + k0 + lkc[it] * 8;\
            size_t gb = (size_t)(nbase + lr[it]) * 1536 + k0 + lkc[it] * 8;\
            cp16(sb + S_AF + lso[it], g_Af + ga);                          \
            cp16(sb + S_BF + lso[it], g_Bf + gb);                          \
        }                                                                  \
    } while (0)

    ISSUE_STAGE(0); CP_COMMIT();
    ISSUE_STAGE(1); CP_COMMIT();

    for (int kb = 0; kb < NKB; kb++) {
        CP_WAIT1();
        __syncthreads();

        if (kb + 2 < NKB) ISSUE_STAGE(kb + 2);
        CP_COMMIT();

        const uint32_t cb = smem_u + (kb % 3) * DSTAGE;
#pragma unroll
        for (int k16 = 0; k16 < 4; k16++) {
            uint32_t a_f[4][4], b_f[2][4];
            {
                int chunk = k16 * 2 + (lane >> 4);
#pragma unroll
                for (int i = 0; i < 4; i++) {
                    int row = wm * 64 + i * 16 + (lane & 15);
                    uint32_t so = (uint32_t)(row * 128 + chunk * 16);
                    so ^= ((so >> 3) & 0x70);
                    ldsm4(a_f[i], cb + S_AF + so);
                }
            }
            {
                int g = lane >> 3;
#pragma unroll
                for (int t = 0; t < 2; t++) {
                    int row = wn * 32 + (t * 2 + (g >> 1)) * 8 + (lane & 7);
                    int chunk = k16 * 2 + (g & 1);
                    uint32_t so = (uint32_t)(row * 128 + chunk * 16);
                    so ^= ((so >> 3) & 0x70);
                    ldsm4(b_f[t], cb + S_BF + so);
                }
            }
#pragma unroll
            for (int i = 0; i < 4; i++)
#pragma unroll
                for (int j = 0; j < 4; j++) {
                    int t = j >> 1, pr = (j & 1) * 2;
                    mma16816h(acc[i][j], a_f[i], b_f[t][pr], b_f[t][pr + 1]);
                }
        }
        __syncthreads();
    }

    // ---- epilogue: C -> smem (n-major, o contiguous, pad 132) -> BN+lrelu -> out ----
    float* Csm = (float*)smem;
#pragma unroll
    for (int i = 0; i < 4; i++)
#pragma unroll
        for (int j = 0; j < 4; j++) {
            int nl = wn * 32 + j * 8 + 2 * (lane & 3);
            int ol = wm * 64 + i * 16 + (lane >> 2);
            Csm[(size_t)nl * 132 + ol]            = acc[i][j][0];
            Csm[(size_t)(nl + 1) * 132 + ol]      = acc[i][j][1];
            Csm[(size_t)nl * 132 + ol + 8]        = acc[i][j][2];
            Csm[(size_t)(nl + 1) * 132 + ol + 8]  = acc[i][j][3];
        }
    __syncthreads();

    for (int idx = tid; idx < 128 * 32; idx += 256) {
        int nl = idx >> 5, o4 = (idx & 31) * 4;
        float4 v = *(const float4*)&Csm[(size_t)nl * 132 + o4];
        v.x = lrelu(v.x * s_sc[o4 + 0] + s_sh[o4 + 0]);
        v.y = lrelu(v.y * s_sc[o4 + 1] + s_sh[o4 + 1]);
        v.z = lrelu(v.z * s_sc[o4 + 2] + s_sh[o4 + 2]);
        v.w = lrelu(v.w * s_sc[o4 + 3] + s_sh[o4 + 3]);
        *(float4*)&out[(size_t)(nbase + nl) * 768 + obase + o4] = v;
    }
}

// =====================================================================================
extern "C" void kernel_launch(void* const* d_in, const int* in_sizes, int n_in,
                              void* d_out, int out_size)
{
    const float* x      = (const float*)d_in[0];
    const float* stem_w = (const float*)d_in[1];
    const float* stem_b = (const float*)d_in[2];
    const float* bn1_g  = (const float*)d_in[3];
    const float* bn1_b  = (const float*)d_in[4];
    const float* bn1_m  = (const float*)d_in[5];
    const float* bn1_v  = (const float*)d_in[6];
    const float* off_w  = (const float*)d_in[7];
    const float* off_b  = (const float*)d_in[8];
    const float* dcn_w  = (const float*)d_in[9];
    const float* dcn_b  = (const float*)d_in[10];
    const float* bn2_g  = (const float*)d_in[11];
    const float* bn2_b  = (const float*)d_in[12];
    const float* bn2_m  = (const float*)d_in[13];
    const float* bn2_v  = (const float*)d_in[14];
    float* out = (float*)d_out;

    cudaFuncSetAttribute(dcn_mma_kernel, cudaFuncAttributeMaxDynamicSharedMemorySize, SMEM_TOTAL);
    cudaFuncSetAttribute(offconv_part_kernel, cudaFuncAttributeMaxDynamicSharedMemorySize, OC_SMEM);

    stem_kernel<<<64 * 49, 256>>>(x, stem_w, stem_b, bn1_g, bn1_b, bn1_m, bn1_v);
    offw_perm_kernel<<<(32 * 1536 + 255) / 256, 256>>>(off_w);
    convw_kernel<<<(768 * 1536 + 255) / 256, 256>>>(dcn_w);
    offconv_part_kernel<<<dim3(98, 8), 512, OC_SMEM>>>();
    offreduce_kernel<<<(32 * 12544 + 255) / 256, 256>>>(off_b);
    gather_kernel<<<64 * 196, 384>>>();
    dcn_mma_kernel<<<dim3(6, 98), 256, SMEM_TOTAL>>>(dcn_b, bn2_g, bn2_b, bn2_m, bn2_v, out);
}